// round 1
// baseline (speedup 1.0000x reference)
#include <cuda_runtime.h>
#include <cuda_bf16.h>
#include <cstddef>

// Problem constants (shapes are fixed by the dataset; n/E still read from in_sizes)
#define NMAX   50000
#define HDIM   256
#define H4     (HDIM / 4)     // 64 float4 per row

// ---------------- scratch (device globals: no allocation allowed) ----------------
__device__ float g_t  [(size_t)NMAX * HDIM];  // GEMM output (pre-aggregation messages)
__device__ float g_y  [(size_t)NMAX * HDIM];  // layer activations (next layer input)
__device__ float g_agg[(size_t)NMAX * HDIM];  // scatter-add accumulator
__device__ float g_dinv[NMAX];                // deg -> rsqrt(deg)
__device__ float g_gv  [HDIM];                // column sums for the mean pool

// ---------------- prep: zero agg + gv, set dinv = 1 (self-loop) ----------------
__global__ void prep_kernel(int n)
{
    int tid = blockIdx.x * blockDim.x + threadIdx.x;
    int total4 = n * H4;
    if (tid < total4)
        reinterpret_cast<float4*>(g_agg)[tid] = make_float4(0.f, 0.f, 0.f, 0.f);
    if (tid < n)    g_dinv[tid] = 1.0f;
    if (tid < HDIM) g_gv[tid]   = 0.0f;
}

// ---------------- degree count (incoming edges) ----------------
__global__ void deg_kernel(const int* __restrict__ dst, int E)
{
    int e = blockIdx.x * blockDim.x + threadIdx.x;
    if (e < E) atomicAdd(&g_dinv[dst[e]], 1.0f);
}

__global__ void rsqrt_kernel(int n)
{
    int i = blockIdx.x * blockDim.x + threadIdx.x;
    if (i < n) g_dinv[i] = rsqrtf(g_dinv[i]);
}

// ---------------- SGEMM: C[M,Nc] = A[M,K] @ B[K,Nc] ----------------
// BM=128 BN=128 BK=8, 256 threads, 8x8 per thread
#define BM 128
#define BN 128
#define BK 8
#define TM 8
#define TN 8

__global__ __launch_bounds__(256, 2)
void sgemm_kernel(const float* __restrict__ A, const float* __restrict__ B,
                  float* __restrict__ C, int M, int Nc, int K)
{
    __shared__ float As[BK][BM];
    __shared__ float Bs[BK][BN];

    const int tid = threadIdx.x;
    const int rowA0 = blockIdx.y * BM;
    const int colB0 = blockIdx.x * BN;

    // A tile loads: 128x8 floats = 256 float4 -> one per thread
    const int aRow = tid >> 1;
    const int aCol = (tid & 1) * 4;
    // B tile loads: 8x128 floats = 256 float4 -> one per thread
    const int bRow = tid >> 5;
    const int bCol = (tid & 31) * 4;

    const int tRow = (tid >> 4) * TM;   // 0..120
    const int tCol = (tid & 15) * TN;   // 0..120

    float acc[TM][TN];
#pragma unroll
    for (int i = 0; i < TM; i++)
#pragma unroll
        for (int j = 0; j < TN; j++) acc[i][j] = 0.0f;

    for (int k0 = 0; k0 < K; k0 += BK) {
        // load A (guard M edge)
        const int gr = rowA0 + aRow;
        float4 a4 = make_float4(0.f, 0.f, 0.f, 0.f);
        if (gr < M)
            a4 = *reinterpret_cast<const float4*>(A + (size_t)gr * K + k0 + aCol);
        As[aCol + 0][aRow] = a4.x;
        As[aCol + 1][aRow] = a4.y;
        As[aCol + 2][aRow] = a4.z;
        As[aCol + 3][aRow] = a4.w;
        // load B (K multiple of 8, Nc multiple of 128 -> no guard needed)
        float4 b4 = *reinterpret_cast<const float4*>(B + (size_t)(k0 + bRow) * Nc + colB0 + bCol);
        *reinterpret_cast<float4*>(&Bs[bRow][bCol]) = b4;
        __syncthreads();

#pragma unroll
        for (int k = 0; k < BK; k++) {
            float regM[TM], regN[TN];
#pragma unroll
            for (int i = 0; i < TM; i++) regM[i] = As[k][tRow + i];
#pragma unroll
            for (int j = 0; j < TN; j++) regN[j] = Bs[k][tCol + j];
#pragma unroll
            for (int i = 0; i < TM; i++)
#pragma unroll
                for (int j = 0; j < TN; j++)
                    acc[i][j] = fmaf(regM[i], regN[j], acc[i][j]);
        }
        __syncthreads();
    }

#pragma unroll
    for (int i = 0; i < TM; i++) {
        const int gr = rowA0 + tRow + i;
        if (gr < M) {
            float* cp = C + (size_t)gr * Nc + colB0 + tCol;
            *reinterpret_cast<float4*>(cp + 0) = make_float4(acc[i][0], acc[i][1], acc[i][2], acc[i][3]);
            *reinterpret_cast<float4*>(cp + 4) = make_float4(acc[i][4], acc[i][5], acc[i][6], acc[i][7]);
        }
    }
}

// ---------------- edge aggregation: agg[dst] += h[src] * dinv[src]*dinv[dst] ----------------
// 64 threads per edge (one float4 each), 4 edges per 256-thread block.
__global__ __launch_bounds__(256)
void aggregate_kernel(const int* __restrict__ src, const int* __restrict__ dst, int E)
{
    const int e = blockIdx.x * 4 + (threadIdx.x >> 6);
    if (e >= E) return;
    const int lane = threadIdx.x & 63;
    const int s = __ldg(src + e);
    const int d = __ldg(dst + e);
    const float c = __ldg(&g_dinv[s]) * __ldg(&g_dinv[d]);
    float4 v = __ldg(reinterpret_cast<const float4*>(g_t) + (size_t)s * H4 + lane);
    v.x *= c; v.y *= c; v.z *= c; v.w *= c;
    atomicAdd(reinterpret_cast<float4*>(g_agg) + (size_t)d * H4 + lane, v);  // cc9.0+ vector atomic
}

// ---------------- finalize: y = relu(agg + h*dinv^2 + b); agg <- 0 (for next use) ----------------
__global__ void finalize_kernel(const float* __restrict__ b, int n)
{
    const int i = blockIdx.x * blockDim.x + threadIdx.x;   // float4 index
    if (i >= n * H4) return;
    const int node = i >> 6;
    const int c4   = i & 63;
    const float dv = g_dinv[node];
    const float d2 = dv * dv;
    float4 hv = reinterpret_cast<const float4*>(g_t)[i];
    float4 av = reinterpret_cast<const float4*>(g_agg)[i];
    float4 bv = reinterpret_cast<const float4*>(b)[c4];
    float4 r;
    r.x = fmaxf(fmaf(hv.x, d2, av.x) + bv.x, 0.0f);
    r.y = fmaxf(fmaf(hv.y, d2, av.y) + bv.y, 0.0f);
    r.z = fmaxf(fmaf(hv.z, d2, av.z) + bv.z, 0.0f);
    r.w = fmaxf(fmaf(hv.w, d2, av.w) + bv.w, 0.0f);
    reinterpret_cast<float4*>(g_y)[i]   = r;
    reinterpret_cast<float4*>(g_agg)[i] = make_float4(0.f, 0.f, 0.f, 0.f);
}

// ---------------- column sums of g_y (for mean pooling) ----------------
__global__ void colsum_kernel(int n)
{
    const int j = threadIdx.x;  // 256 threads == HDIM
    float s = 0.0f;
    for (int r = blockIdx.x; r < n; r += gridDim.x)
        s += g_y[(size_t)r * HDIM + j];
    atomicAdd(&g_gv[j], s);
}

// ---------------- final linear: out = (gv/n) @ Wl + bl ----------------
__global__ void final_kernel(const float* __restrict__ Wl, const float* __restrict__ bl,
                             float* __restrict__ out, float invN)
{
    __shared__ float s[2];
    if (threadIdx.x < 2) s[threadIdx.x] = 0.0f;
    __syncthreads();
    const int j = threadIdx.x;  // 256 threads
    const float gj = g_gv[j] * invN;
    atomicAdd(&s[0], gj * Wl[j * 2 + 0]);
    atomicAdd(&s[1], gj * Wl[j * 2 + 1]);
    __syncthreads();
    if (threadIdx.x < 2) out[threadIdx.x] = s[threadIdx.x] + bl[threadIdx.x];
}

// ---------------- launcher ----------------
extern "C" void kernel_launch(void* const* d_in, const int* in_sizes, int n_in,
                              void* d_out, int out_size)
{
    const float* x  = (const float*)d_in[0];
    const int*   ei = (const int*)  d_in[1];
    // d_in[2] = batch (unused, all zeros)
    const float* W1 = (const float*)d_in[3];
    const float* b1 = (const float*)d_in[4];
    const float* W2 = (const float*)d_in[5];
    const float* b2 = (const float*)d_in[6];
    const float* Wl = (const float*)d_in[7];
    const float* bl = (const float*)d_in[8];
    float* out = (float*)d_out;

    const int n = in_sizes[0] / 128;   // 50000
    const int E = in_sizes[1] / 2;     // 800000
    const int F_IN = 128;

    const int* src = ei;
    const int* dst = ei + E;

    float* t_ptr;  cudaGetSymbolAddress((void**)&t_ptr,  g_t);
    float* y_ptr;  cudaGetSymbolAddress((void**)&y_ptr,  g_y);

    const int total4 = n * H4;

    // prep: zero agg/gv, dinv=1
    prep_kernel<<<(total4 + 255) / 256, 256>>>(n);
    // degrees -> dinv
    deg_kernel<<<(E + 255) / 256, 256>>>(dst, E);
    rsqrt_kernel<<<(n + 255) / 256, 256>>>(n);

    dim3 gemmGrid(HDIM / BN, (n + BM - 1) / BM);

    // ---- layer 1 ----
    sgemm_kernel<<<gemmGrid, 256>>>(x, W1, t_ptr, n, HDIM, F_IN);
    aggregate_kernel<<<(E + 3) / 4, 256>>>(src, dst, E);
    finalize_kernel<<<(total4 + 255) / 256, 256>>>(b1, n);

    // ---- layer 2 ----
    sgemm_kernel<<<gemmGrid, 256>>>(y_ptr, W2, t_ptr, n, HDIM, HDIM);
    aggregate_kernel<<<(E + 3) / 4, 256>>>(src, dst, E);
    finalize_kernel<<<(total4 + 255) / 256, 256>>>(b2, n);

    // ---- mean pool + final linear ----
    colsum_kernel<<<592, HDIM>>>(n);
    final_kernel<<<1, HDIM>>>(Wl, bl, out, 1.0f / (float)n);
}

// round 2
// speedup vs baseline: 1.5346x; 1.5346x over previous
#include <cuda_runtime.h>
#include <cuda_bf16.h>
#include <cstddef>

#define NMAX   50000
#define EMAX   800000
#define HDIM   256
#define H4     (HDIM / 4)     // 64 float4 per row
#define SCAN_B 256            // scan chunk

// ---------------- scratch (device globals) ----------------
__device__ float g_t   [(size_t)NMAX * HDIM];  // GEMM output (messages)
__device__ float g_y   [(size_t)NMAX * HDIM];  // layer activations
__device__ float g_dinv[NMAX];                 // rsqrt(deg+1)
__device__ int   g_degi[NMAX];                 // in-degree
__device__ int   g_off [NMAX + 1];             // CSR offsets
__device__ int   g_cur [NMAX];                 // scatter cursors
__device__ int   g_csrc[EMAX];                 // CSR src indices
__device__ int   g_part[512];                  // scan partials
__device__ float g_gv  [HDIM];                 // column sums (mean pool)

// ---------------- prep ----------------
__global__ void prep_kernel(int n)
{
    int i = blockIdx.x * blockDim.x + threadIdx.x;
    if (i < n)    g_degi[i] = 0;
    if (i < HDIM) g_gv[i]   = 0.0f;
}

// ---------------- degree count ----------------
__global__ void deg_kernel(const int* __restrict__ dst, int E)
{
    int e = blockIdx.x * blockDim.x + threadIdx.x;
    if (e < E) atomicAdd(&g_degi[dst[e]], 1);
}

// ---------------- dinv = rsqrt(deg+1) ----------------
__global__ void rsqrt_kernel(int n)
{
    int i = blockIdx.x * blockDim.x + threadIdx.x;
    if (i < n) g_dinv[i] = rsqrtf((float)g_degi[i] + 1.0f);
}

// ---------------- scan step 1: per-block sums of degrees ----------------
__global__ void scan1_kernel(int n)
{
    __shared__ int s[SCAN_B];
    int i = blockIdx.x * SCAN_B + threadIdx.x;
    s[threadIdx.x] = (i < n) ? g_degi[i] : 0;
    __syncthreads();
    for (int ofs = SCAN_B / 2; ofs > 0; ofs >>= 1) {
        if (threadIdx.x < ofs) s[threadIdx.x] += s[threadIdx.x + ofs];
        __syncthreads();
    }
    if (threadIdx.x == 0) g_part[blockIdx.x] = s[0];
}

// ---------------- scan step 2: exclusive scan of partials (1 block) ----------------
__global__ void scan2_kernel(int nblocks, int n, int E)
{
    __shared__ int a[512], b[512];
    int t = threadIdx.x;          // 512 threads
    int v = (t < nblocks) ? g_part[t] : 0;
    a[t] = v;
    __syncthreads();
    int* pin = a; int* pout = b;
    for (int ofs = 1; ofs < 512; ofs <<= 1) {
        pout[t] = (t >= ofs) ? pin[t] + pin[t - ofs] : pin[t];
        __syncthreads();
        int* tmp = pin; pin = pout; pout = tmp;
    }
    // pin holds inclusive scan -> exclusive
    g_part[t] = (t == 0) ? 0 : pin[t - 1];
    if (t == 0) g_off[n] = E;
}

// ---------------- scan step 3: per-block exclusive scan + base; write off & cur ----------------
__global__ void scan3_kernel(int n)
{
    __shared__ int a[SCAN_B], b[SCAN_B];
    int t = threadIdx.x;
    int i = blockIdx.x * SCAN_B + t;
    int v = (i < n) ? g_degi[i] : 0;
    a[t] = v;
    __syncthreads();
    int* pin = a; int* pout = b;
    for (int ofs = 1; ofs < SCAN_B; ofs <<= 1) {
        pout[t] = (t >= ofs) ? pin[t] + pin[t - ofs] : pin[t];
        __syncthreads();
        int* tmp = pin; pin = pout; pout = tmp;
    }
    if (i < n) {
        int excl = (t == 0) ? 0 : pin[t - 1];
        int off = g_part[blockIdx.x] + excl;
        g_off[i] = off;
        g_cur[i] = off;
    }
}

// ---------------- scatter edges into CSR buckets ----------------
__global__ void scatter_kernel(const int* __restrict__ src, const int* __restrict__ dst, int E)
{
    int e = blockIdx.x * blockDim.x + threadIdx.x;
    if (e < E) {
        int d = dst[e];
        int pos = atomicAdd(&g_cur[d], 1);
        g_csrc[pos] = src[e];
    }
}

// ---------------- SGEMM: C[M,Nc] = A[M,K] @ B[K,Nc] ----------------
#define BM 128
#define BN 128
#define BK 8
#define TM 8
#define TN 8

__global__ __launch_bounds__(256, 2)
void sgemm_kernel(const float* __restrict__ A, const float* __restrict__ B,
                  float* __restrict__ C, int M, int Nc, int K)
{
    __shared__ float As[BK][BM];
    __shared__ float Bs[BK][BN];

    const int tid = threadIdx.x;
    const int rowA0 = blockIdx.y * BM;
    const int colB0 = blockIdx.x * BN;

    const int aRow = tid >> 1;
    const int aCol = (tid & 1) * 4;
    const int bRow = tid >> 5;
    const int bCol = (tid & 31) * 4;

    const int tRow = (tid >> 4) * TM;
    const int tCol = (tid & 15) * TN;

    float acc[TM][TN];
#pragma unroll
    for (int i = 0; i < TM; i++)
#pragma unroll
        for (int j = 0; j < TN; j++) acc[i][j] = 0.0f;

    for (int k0 = 0; k0 < K; k0 += BK) {
        const int gr = rowA0 + aRow;
        float4 a4 = make_float4(0.f, 0.f, 0.f, 0.f);
        if (gr < M)
            a4 = *reinterpret_cast<const float4*>(A + (size_t)gr * K + k0 + aCol);
        As[aCol + 0][aRow] = a4.x;
        As[aCol + 1][aRow] = a4.y;
        As[aCol + 2][aRow] = a4.z;
        As[aCol + 3][aRow] = a4.w;
        float4 b4 = *reinterpret_cast<const float4*>(B + (size_t)(k0 + bRow) * Nc + colB0 + bCol);
        *reinterpret_cast<float4*>(&Bs[bRow][bCol]) = b4;
        __syncthreads();

#pragma unroll
        for (int k = 0; k < BK; k++) {
            float regM[TM], regN[TN];
#pragma unroll
            for (int i = 0; i < TM; i++) regM[i] = As[k][tRow + i];
#pragma unroll
            for (int j = 0; j < TN; j++) regN[j] = Bs[k][tCol + j];
#pragma unroll
            for (int i = 0; i < TM; i++)
#pragma unroll
                for (int j = 0; j < TN; j++)
                    acc[i][j] = fmaf(regM[i], regN[j], acc[i][j]);
        }
        __syncthreads();
    }

#pragma unroll
    for (int i = 0; i < TM; i++) {
        const int gr = rowA0 + tRow + i;
        if (gr < M) {
            float* cp = C + (size_t)gr * Nc + colB0 + tCol;
            *reinterpret_cast<float4*>(cp + 0) = make_float4(acc[i][0], acc[i][1], acc[i][2], acc[i][3]);
            *reinterpret_cast<float4*>(cp + 4) = make_float4(acc[i][4], acc[i][5], acc[i][6], acc[i][7]);
        }
    }
}

// ---------------- pull aggregation + finalize ----------------
// One warp per destination node. Each lane owns 8 columns (2 float4).
// y[d] = relu( dinv[d] * sum_e dinv[src_e] * t[src_e]  +  t[d]*dinv[d]^2  +  b )
__global__ __launch_bounds__(256)
void pull_kernel(const float* __restrict__ b, int n)
{
    const int warp = blockIdx.x * 8 + (threadIdx.x >> 5);
    if (warp >= n) return;
    const int lane = threadIdx.x & 31;
    const int d = warp;

    const int beg = g_off[d];
    const int end = g_off[d + 1];

    const float4* __restrict__ T = reinterpret_cast<const float4*>(g_t);
    const size_t lofs = (size_t)lane * 2;

    float4 acc0 = make_float4(0.f, 0.f, 0.f, 0.f);
    float4 acc1 = make_float4(0.f, 0.f, 0.f, 0.f);

    for (int base = beg; base < end; base += 32) {
        const int e = base + lane;
        int   s  = (e < end) ? __ldg(&g_csrc[e]) : 0;
        float dv = (e < end) ? __ldg(&g_dinv[s]) : 0.0f;
        const int cnt = min(32, end - base);
#pragma unroll 4
        for (int j = 0; j < cnt; j++) {
            const int   sj = __shfl_sync(0xffffffffu, s, j);
            const float cj = __shfl_sync(0xffffffffu, dv, j);
            const float4* row = T + (size_t)sj * H4 + lofs;
            float4 v0 = __ldg(row);
            float4 v1 = __ldg(row + 1);
            acc0.x = fmaf(cj, v0.x, acc0.x);
            acc0.y = fmaf(cj, v0.y, acc0.y);
            acc0.z = fmaf(cj, v0.z, acc0.z);
            acc0.w = fmaf(cj, v0.w, acc0.w);
            acc1.x = fmaf(cj, v1.x, acc1.x);
            acc1.y = fmaf(cj, v1.y, acc1.y);
            acc1.z = fmaf(cj, v1.z, acc1.z);
            acc1.w = fmaf(cj, v1.w, acc1.w);
        }
    }

    const float dd = g_dinv[d];
    const float d2 = dd * dd;
    const float4* hrow = T + (size_t)d * H4 + lofs;
    float4 h0 = __ldg(hrow);
    float4 h1 = __ldg(hrow + 1);
    const float4* bp = reinterpret_cast<const float4*>(b) + lofs;
    float4 b0 = __ldg(bp);
    float4 b1 = __ldg(bp + 1);

    float4 r0, r1;
    r0.x = fmaxf(fmaf(dd, acc0.x, fmaf(d2, h0.x, b0.x)), 0.0f);
    r0.y = fmaxf(fmaf(dd, acc0.y, fmaf(d2, h0.y, b0.y)), 0.0f);
    r0.z = fmaxf(fmaf(dd, acc0.z, fmaf(d2, h0.z, b0.z)), 0.0f);
    r0.w = fmaxf(fmaf(dd, acc0.w, fmaf(d2, h0.w, b0.w)), 0.0f);
    r1.x = fmaxf(fmaf(dd, acc1.x, fmaf(d2, h1.x, b1.x)), 0.0f);
    r1.y = fmaxf(fmaf(dd, acc1.y, fmaf(d2, h1.y, b1.y)), 0.0f);
    r1.z = fmaxf(fmaf(dd, acc1.z, fmaf(d2, h1.z, b1.z)), 0.0f);
    r1.w = fmaxf(fmaf(dd, acc1.w, fmaf(d2, h1.w, b1.w)), 0.0f);

    float4* yp = reinterpret_cast<float4*>(g_y) + (size_t)d * H4 + lofs;
    yp[0] = r0;
    yp[1] = r1;
}

// ---------------- column sums of g_y ----------------
__global__ void colsum_kernel(int n)
{
    const int j = threadIdx.x;  // 256 threads == HDIM
    float s = 0.0f;
    for (int r = blockIdx.x; r < n; r += gridDim.x)
        s += g_y[(size_t)r * HDIM + j];
    atomicAdd(&g_gv[j], s);
}

// ---------------- final linear ----------------
__global__ void final_kernel(const float* __restrict__ Wl, const float* __restrict__ bl,
                             float* __restrict__ out, float invN)
{
    __shared__ float s[2];
    if (threadIdx.x < 2) s[threadIdx.x] = 0.0f;
    __syncthreads();
    const int j = threadIdx.x;
    const float gj = g_gv[j] * invN;
    atomicAdd(&s[0], gj * Wl[j * 2 + 0]);
    atomicAdd(&s[1], gj * Wl[j * 2 + 1]);
    __syncthreads();
    if (threadIdx.x < 2) out[threadIdx.x] = s[threadIdx.x] + bl[threadIdx.x];
}

// ---------------- launcher ----------------
extern "C" void kernel_launch(void* const* d_in, const int* in_sizes, int n_in,
                              void* d_out, int out_size)
{
    const float* x  = (const float*)d_in[0];
    const int*   ei = (const int*)  d_in[1];
    const float* W1 = (const float*)d_in[3];
    const float* b1 = (const float*)d_in[4];
    const float* W2 = (const float*)d_in[5];
    const float* b2 = (const float*)d_in[6];
    const float* Wl = (const float*)d_in[7];
    const float* bl = (const float*)d_in[8];
    float* out = (float*)d_out;

    const int n = in_sizes[0] / 128;   // 50000
    const int E = in_sizes[1] / 2;     // 800000
    const int F_IN = 128;

    const int* src = ei;
    const int* dst = ei + E;

    float* t_ptr;  cudaGetSymbolAddress((void**)&t_ptr,  g_t);
    float* y_ptr;  cudaGetSymbolAddress((void**)&y_ptr,  g_y);

    const int nScanBlocks = (n + SCAN_B - 1) / SCAN_B;   // 196

    // ---- graph preprocessing: degrees, dinv, CSR ----
    prep_kernel<<<(n + 255) / 256, 256>>>(n);
    deg_kernel<<<(E + 255) / 256, 256>>>(dst, E);
    rsqrt_kernel<<<(n + 255) / 256, 256>>>(n);
    scan1_kernel<<<nScanBlocks, SCAN_B>>>(n);
    scan2_kernel<<<1, 512>>>(nScanBlocks, n, E);
    scan3_kernel<<<nScanBlocks, SCAN_B>>>(n);
    scatter_kernel<<<(E + 255) / 256, 256>>>(src, dst, E);

    dim3 gemmGrid(HDIM / BN, (n + BM - 1) / BM);
    const int pullBlocks = (n + 7) / 8;

    // ---- layer 1 ----
    sgemm_kernel<<<gemmGrid, 256>>>(x, W1, t_ptr, n, HDIM, F_IN);
    pull_kernel<<<pullBlocks, 256>>>(b1, n);

    // ---- layer 2 ----
    sgemm_kernel<<<gemmGrid, 256>>>(y_ptr, W2, t_ptr, n, HDIM, HDIM);
    pull_kernel<<<pullBlocks, 256>>>(b2, n);

    // ---- mean pool + final linear ----
    colsum_kernel<<<592, HDIM>>>(n);
    final_kernel<<<1, HDIM>>>(Wl, bl, out, 1.0f / (float)n);
}

// round 4
// speedup vs baseline: 2.2717x; 1.4804x over previous
#include <cuda_runtime.h>
#include <cuda_bf16.h>
#include <cstddef>
#include <cstdint>

#define NMAX   50000
#define EMAX   800000
#define HDIM   256
#define H4     (HDIM / 4)
#define SCAN_B 256

// ---------------- scratch (device globals) ----------------
__device__ __align__(16) float g_t   [(size_t)NMAX * HDIM];
__device__ __align__(16) float g_y   [(size_t)NMAX * HDIM];
__device__ float g_dinv[NMAX];
__device__ int   g_degi[NMAX];
__device__ int   g_off [NMAX + 1];
__device__ int   g_cur [NMAX];
__device__ int   g_csrc[EMAX];
__device__ int   g_part[512];
__device__ float g_gv  [HDIM];
// bf16 split weights, transposed to [n][k]
__device__ __align__(16) __nv_bfloat16 g_w1t_hi[HDIM * 128];
__device__ __align__(16) __nv_bfloat16 g_w1t_lo[HDIM * 128];
__device__ __align__(16) __nv_bfloat16 g_w2t_hi[HDIM * HDIM];
__device__ __align__(16) __nv_bfloat16 g_w2t_lo[HDIM * HDIM];

// ---------------- helpers ----------------
__device__ __forceinline__ uint32_t smem_u32(const void* p) {
    uint32_t a;
    asm("{ .reg .u64 t; cvta.to.shared.u64 t, %1; cvt.u32.u64 %0, t; }" : "=r"(a) : "l"(p));
    return a;
}
#define SWZ(off) ((off) ^ (((off) >> 3) & 0x70))

__device__ __forceinline__ void ldsm_x4(uint32_t addr, uint32_t& r0, uint32_t& r1,
                                        uint32_t& r2, uint32_t& r3) {
    asm volatile("ldmatrix.sync.aligned.m8n8.x4.shared.b16 {%0,%1,%2,%3}, [%4];"
                 : "=r"(r0), "=r"(r1), "=r"(r2), "=r"(r3) : "r"(addr));
}

__device__ __forceinline__ void mma_bf16(float* d, const uint32_t* a, const uint32_t* b) {
    asm volatile("mma.sync.aligned.m16n8k16.row.col.f32.bf16.bf16.f32 "
                 "{%0,%1,%2,%3}, {%4,%5,%6,%7}, {%8,%9}, {%0,%1,%2,%3};"
                 : "+f"(d[0]), "+f"(d[1]), "+f"(d[2]), "+f"(d[3])
                 : "r"(a[0]), "r"(a[1]), "r"(a[2]), "r"(a[3]), "r"(b[0]), "r"(b[1]));
}

// ---------------- prep ----------------
__global__ void prep_kernel(int n)
{
    int i = blockIdx.x * blockDim.x + threadIdx.x;
    if (i < n)    g_degi[i] = 0;
    if (i < HDIM) g_gv[i]   = 0.0f;
}

__global__ void deg_kernel(const int* __restrict__ dst, int E)
{
    int e = blockIdx.x * blockDim.x + threadIdx.x;
    if (e < E) atomicAdd(&g_degi[dst[e]], 1);
}

__global__ void rsqrt_kernel(int n)
{
    int i = blockIdx.x * blockDim.x + threadIdx.x;
    if (i < n) g_dinv[i] = rsqrtf((float)g_degi[i] + 1.0f);
}

// ---------------- weight transpose + bf16 split: out[n*K+k] = W[k*N+n] ----------------
__global__ void wtrans_kernel(const float* __restrict__ W,
                              __nv_bfloat16* __restrict__ hi, __nv_bfloat16* __restrict__ lo,
                              int K, int N)
{
    int idx = blockIdx.x * 256 + threadIdx.x;
    if (idx >= N * K) return;
    int nn = idx / K, kk = idx - nn * K;
    float w = W[(size_t)kk * N + nn];
    __nv_bfloat16 h = __float2bfloat16_rn(w);
    float r = w - __bfloat162float(h);
    hi[idx] = h;
    lo[idx] = __float2bfloat16_rn(r);
}

// ---------------- scan ----------------
__global__ void scan1_kernel(int n)
{
    __shared__ int s[SCAN_B];
    int i = blockIdx.x * SCAN_B + threadIdx.x;
    s[threadIdx.x] = (i < n) ? g_degi[i] : 0;
    __syncthreads();
    for (int ofs = SCAN_B / 2; ofs > 0; ofs >>= 1) {
        if (threadIdx.x < ofs) s[threadIdx.x] += s[threadIdx.x + ofs];
        __syncthreads();
    }
    if (threadIdx.x == 0) g_part[blockIdx.x] = s[0];
}

__global__ void scan2_kernel(int nblocks, int n, int E)
{
    __shared__ int a[512], b[512];
    int t = threadIdx.x;
    int v = (t < nblocks) ? g_part[t] : 0;
    a[t] = v;
    __syncthreads();
    int* pin = a; int* pout = b;
    for (int ofs = 1; ofs < 512; ofs <<= 1) {
        pout[t] = (t >= ofs) ? pin[t] + pin[t - ofs] : pin[t];
        __syncthreads();
        int* tmp = pin; pin = pout; pout = tmp;
    }
    g_part[t] = (t == 0) ? 0 : pin[t - 1];
    if (t == 0) g_off[n] = E;
}

__global__ void scan3_kernel(int n)
{
    __shared__ int a[SCAN_B], b[SCAN_B];
    int t = threadIdx.x;
    int i = blockIdx.x * SCAN_B + t;
    int v = (i < n) ? g_degi[i] : 0;
    a[t] = v;
    __syncthreads();
    int* pin = a; int* pout = b;
    for (int ofs = 1; ofs < SCAN_B; ofs <<= 1) {
        pout[t] = (t >= ofs) ? pin[t] + pin[t - ofs] : pin[t];
        __syncthreads();
        int* tmp = pin; pin = pout; pout = tmp;
    }
    if (i < n) {
        int excl = (t == 0) ? 0 : pin[t - 1];
        int off = g_part[blockIdx.x] + excl;
        g_off[i] = off;
        g_cur[i] = off;
    }
}

__global__ void scatter_kernel(const int* __restrict__ src, const int* __restrict__ dst, int E)
{
    int e = blockIdx.x * blockDim.x + threadIdx.x;
    if (e < E) {
        int d = dst[e];
        int pos = atomicAdd(&g_cur[d], 1);
        g_csrc[pos] = src[e];
    }
}

// ---------------- HMMA GEMM: C[M,256] = A[M,K] @ W[K,256], split bf16 ----------------
// CTA 128x128, BK=64, 8 warps (warp tile 32x64). mma.sync m16n8k16 bf16, fp32 acc.
#define SA_HI 0
#define SA_LO 16384
#define SB_HI 32768
#define SB_LO 49152
#define SM_TOTAL 65536

__global__ __launch_bounds__(256, 1)
void tgemm_kernel(const float* __restrict__ A,
                  const __nv_bfloat16* __restrict__ WHI,
                  const __nv_bfloat16* __restrict__ WLO,
                  float* __restrict__ C, int M, int K)
{
    extern __shared__ char smem[];
    const uint32_t sb = smem_u32(smem);
    const int tid = threadIdx.x;
    const int wid = tid >> 5;
    const int lane = tid & 31;
    const int warp_m = wid & 3;     // 0..3 -> 32 rows each
    const int warp_n = wid >> 2;    // 0..1 -> 64 cols each
    const int row0 = blockIdx.x * 128;
    const int col0 = blockIdx.y * 128;

    float acc[2][8][4];
#pragma unroll
    for (int mt = 0; mt < 2; mt++)
#pragma unroll
        for (int nt = 0; nt < 8; nt++)
#pragma unroll
            for (int q = 0; q < 4; q++) acc[mt][nt][q] = 0.0f;

    // ldmatrix per-lane address components
    const int lr   = lane & 7;          // row within 8
    const int lsel = lane >> 3;         // 0..3 matrix select

    for (int k0 = 0; k0 < K; k0 += 64) {
        // ---- stage A [128 x 64 fp32] -> bf16 hi/lo into SW128 smem ----
#pragma unroll
        for (int i = 0; i < 8; i++) {
            const int idx = tid + (i << 8);
            const int row = idx >> 4;
            const int f   = idx & 15;       // float4 index within 64 floats
            const int grow = row0 + row;
            float4 a4 = make_float4(0.f, 0.f, 0.f, 0.f);
            if (grow < M)
                a4 = *reinterpret_cast<const float4*>(A + (size_t)grow * K + k0 + f * 4);
            __nv_bfloat16 h0 = __float2bfloat16_rn(a4.x);
            __nv_bfloat16 h1 = __float2bfloat16_rn(a4.y);
            __nv_bfloat16 h2 = __float2bfloat16_rn(a4.z);
            __nv_bfloat16 h3 = __float2bfloat16_rn(a4.w);
            __nv_bfloat16 l0 = __float2bfloat16_rn(a4.x - __bfloat162float(h0));
            __nv_bfloat16 l1 = __float2bfloat16_rn(a4.y - __bfloat162float(h1));
            __nv_bfloat16 l2 = __float2bfloat16_rn(a4.z - __bfloat162float(h2));
            __nv_bfloat16 l3 = __float2bfloat16_rn(a4.w - __bfloat162float(h3));
            __nv_bfloat162 ph0; ph0.x = h0; ph0.y = h1;
            __nv_bfloat162 ph1; ph1.x = h2; ph1.y = h3;
            __nv_bfloat162 pl0; pl0.x = l0; pl0.y = l1;
            __nv_bfloat162 pl1; pl1.x = l2; pl1.y = l3;
            uint2 uh, ul;
            uh.x = *reinterpret_cast<uint32_t*>(&ph0);
            uh.y = *reinterpret_cast<uint32_t*>(&ph1);
            ul.x = *reinterpret_cast<uint32_t*>(&pl0);
            ul.y = *reinterpret_cast<uint32_t*>(&pl1);
            const uint32_t sw = SWZ(row * 128 + f * 8);
            *reinterpret_cast<uint2*>(smem + SA_HI + sw) = uh;
            *reinterpret_cast<uint2*>(smem + SA_LO + sw) = ul;
        }
        // ---- stage B [128 n-rows x 64 k] hi/lo ----
#pragma unroll
        for (int i = 0; i < 4; i++) {
            const int idx = tid + (i << 8);
            const int nr = idx >> 3;
            const int u  = idx & 7;
            const uint32_t sw = SWZ(nr * 128 + u * 16);
            *reinterpret_cast<uint4*>(smem + SB_HI + sw) =
                *(reinterpret_cast<const uint4*>(WHI + (size_t)(col0 + nr) * K + k0) + u);
            *reinterpret_cast<uint4*>(smem + SB_LO + sw) =
                *(reinterpret_cast<const uint4*>(WLO + (size_t)(col0 + nr) * K + k0) + u);
        }
        __syncthreads();

        // ---- 4 x k16 steps ----
#pragma unroll
        for (int kk = 0; kk < 4; kk++) {
            const int kb = kk * 32 + (lsel & 2) * 8;   // byte offset of k within row (16 bf16 = 32B; +16B for k+8)
            // A fragments: 2 m16 tiles, hi & lo
            uint32_t ah[8], al[8];
#pragma unroll
            for (int mt = 0; mt < 2; mt++) {
                const int arow = warp_m * 32 + mt * 16 + (lsel & 1) * 8 + lr;
                const uint32_t aoff = SWZ(arow * 128 + kb);
                ldsm_x4(sb + SA_HI + aoff, ah[mt*4+0], ah[mt*4+1], ah[mt*4+2], ah[mt*4+3]);
                ldsm_x4(sb + SA_LO + aoff, al[mt*4+0], al[mt*4+1], al[mt*4+2], al[mt*4+3]);
            }
            // B fragments: 8 n8 tiles (4 x4-loads), hi & lo
            // x4 lane map: sel0 -> (n0..7, k), sel1 -> (n0..7, k+8), sel2 -> (n8..15, k), sel3 -> (n8..15, k+8)
            uint32_t bh[16], bl[16];
#pragma unroll
            for (int p = 0; p < 4; p++) {
                const int brow = warp_n * 64 + p * 16 + (lsel >> 1) * 8 + lr;
                const uint32_t boff = SWZ(brow * 128 + kk * 32 + (lsel & 1) * 16);
                ldsm_x4(sb + SB_HI + boff, bh[p*4+0], bh[p*4+1], bh[p*4+2], bh[p*4+3]);
                ldsm_x4(sb + SB_LO + boff, bl[p*4+0], bl[p*4+1], bl[p*4+2], bl[p*4+3]);
            }
#pragma unroll
            for (int mt = 0; mt < 2; mt++) {
#pragma unroll
                for (int nt = 0; nt < 8; nt++) {
                    mma_bf16(acc[mt][nt], &ah[mt*4], &bh[nt*2]);
                    mma_bf16(acc[mt][nt], &al[mt*4], &bh[nt*2]);
                    mma_bf16(acc[mt][nt], &ah[mt*4], &bl[nt*2]);
                }
            }
        }
        __syncthreads();
    }

    // ---- epilogue: direct register stores ----
    const int tr = lane >> 2;        // 0..7
    const int tc = (lane & 3) * 2;   // 0,2,4,6
#pragma unroll
    for (int mt = 0; mt < 2; mt++) {
#pragma unroll
        for (int nt = 0; nt < 8; nt++) {
            const int col = col0 + warp_n * 64 + nt * 8 + tc;
            const int r0 = row0 + warp_m * 32 + mt * 16 + tr;
            if (r0 < M) {
                float2 v; v.x = acc[mt][nt][0]; v.y = acc[mt][nt][1];
                *reinterpret_cast<float2*>(C + (size_t)r0 * HDIM + col) = v;
            }
            if (r0 + 8 < M) {
                float2 v; v.x = acc[mt][nt][2]; v.y = acc[mt][nt][3];
                *reinterpret_cast<float2*>(C + (size_t)(r0 + 8) * HDIM + col) = v;
            }
        }
    }
}

// ---------------- pull aggregation + finalize ----------------
__global__ __launch_bounds__(256)
void pull_kernel(const float* __restrict__ b, int n)
{
    const int warp = blockIdx.x * 8 + (threadIdx.x >> 5);
    if (warp >= n) return;
    const int lane = threadIdx.x & 31;
    const int d = warp;

    const int beg = g_off[d];
    const int end = g_off[d + 1];

    const float4* __restrict__ T = reinterpret_cast<const float4*>(g_t);
    const size_t lofs = (size_t)lane * 2;

    float4 acc0 = make_float4(0.f, 0.f, 0.f, 0.f);
    float4 acc1 = make_float4(0.f, 0.f, 0.f, 0.f);

    for (int base = beg; base < end; base += 32) {
        const int e = base + lane;
        int   s  = (e < end) ? __ldg(&g_csrc[e]) : 0;
        float dv = (e < end) ? __ldg(&g_dinv[s]) : 0.0f;
        const int cnt = min(32, end - base);
#pragma unroll 4
        for (int j = 0; j < cnt; j++) {
            const int   sj = __shfl_sync(0xffffffffu, s, j);
            const float cj = __shfl_sync(0xffffffffu, dv, j);
            const float4* row = T + (size_t)sj * H4 + lofs;
            float4 v0 = __ldg(row);
            float4 v1 = __ldg(row + 1);
            acc0.x = fmaf(cj, v0.x, acc0.x);
            acc0.y = fmaf(cj, v0.y, acc0.y);
            acc0.z = fmaf(cj, v0.z, acc0.z);
            acc0.w = fmaf(cj, v0.w, acc0.w);
            acc1.x = fmaf(cj, v1.x, acc1.x);
            acc1.y = fmaf(cj, v1.y, acc1.y);
            acc1.z = fmaf(cj, v1.z, acc1.z);
            acc1.w = fmaf(cj, v1.w, acc1.w);
        }
    }

    const float dd = g_dinv[d];
    const float d2 = dd * dd;
    const float4* hrow = T + (size_t)d * H4 + lofs;
    float4 h0 = __ldg(hrow);
    float4 h1 = __ldg(hrow + 1);
    const float4* bp = reinterpret_cast<const float4*>(b) + lofs;
    float4 b0 = __ldg(bp);
    float4 b1 = __ldg(bp + 1);

    float4 r0, r1;
    r0.x = fmaxf(fmaf(dd, acc0.x, fmaf(d2, h0.x, b0.x)), 0.0f);
    r0.y = fmaxf(fmaf(dd, acc0.y, fmaf(d2, h0.y, b0.y)), 0.0f);
    r0.z = fmaxf(fmaf(dd, acc0.z, fmaf(d2, h0.z, b0.z)), 0.0f);
    r0.w = fmaxf(fmaf(dd, acc0.w, fmaf(d2, h0.w, b0.w)), 0.0f);
    r1.x = fmaxf(fmaf(dd, acc1.x, fmaf(d2, h1.x, b1.x)), 0.0f);
    r1.y = fmaxf(fmaf(dd, acc1.y, fmaf(d2, h1.y, b1.y)), 0.0f);
    r1.z = fmaxf(fmaf(dd, acc1.z, fmaf(d2, h1.z, b1.z)), 0.0f);
    r1.w = fmaxf(fmaf(dd, acc1.w, fmaf(d2, h1.w, b1.w)), 0.0f);

    float4* yp = reinterpret_cast<float4*>(g_y) + (size_t)d * H4 + lofs;
    yp[0] = r0;
    yp[1] = r1;
}

// ---------------- column sums ----------------
__global__ void colsum_kernel(int n)
{
    const int j = threadIdx.x;
    float s = 0.0f;
    for (int r = blockIdx.x; r < n; r += gridDim.x)
        s += g_y[(size_t)r * HDIM + j];
    atomicAdd(&g_gv[j], s);
}

// ---------------- final linear ----------------
__global__ void final_kernel(const float* __restrict__ Wl, const float* __restrict__ bl,
                             float* __restrict__ out, float invN)
{
    __shared__ float s[2];
    if (threadIdx.x < 2) s[threadIdx.x] = 0.0f;
    __syncthreads();
    const int j = threadIdx.x;
    const float gj = g_gv[j] * invN;
    atomicAdd(&s[0], gj * Wl[j * 2 + 0]);
    atomicAdd(&s[1], gj * Wl[j * 2 + 1]);
    __syncthreads();
    if (threadIdx.x < 2) out[threadIdx.x] = s[threadIdx.x] + bl[threadIdx.x];
}

// ---------------- launcher ----------------
extern "C" void kernel_launch(void* const* d_in, const int* in_sizes, int n_in,
                              void* d_out, int out_size)
{
    const float* x  = (const float*)d_in[0];
    const int*   ei = (const int*)  d_in[1];
    const float* W1 = (const float*)d_in[3];
    const float* b1 = (const float*)d_in[4];
    const float* W2 = (const float*)d_in[5];
    const float* b2 = (const float*)d_in[6];
    const float* Wl = (const float*)d_in[7];
    const float* bl = (const float*)d_in[8];
    float* out = (float*)d_out;

    const int n = in_sizes[0] / 128;   // 50000
    const int E = in_sizes[1] / 2;     // 800000

    const int* src = ei;
    const int* dst = ei + E;

    float* t_ptr;  cudaGetSymbolAddress((void**)&t_ptr,  g_t);
    float* y_ptr;  cudaGetSymbolAddress((void**)&y_ptr,  g_y);
    __nv_bfloat16 *w1h, *w1l, *w2h, *w2l;
    cudaGetSymbolAddress((void**)&w1h, g_w1t_hi);
    cudaGetSymbolAddress((void**)&w1l, g_w1t_lo);
    cudaGetSymbolAddress((void**)&w2h, g_w2t_hi);
    cudaGetSymbolAddress((void**)&w2l, g_w2t_lo);

    cudaFuncSetAttribute(tgemm_kernel, cudaFuncAttributeMaxDynamicSharedMemorySize, SM_TOTAL);

    const int nScanBlocks = (n + SCAN_B - 1) / SCAN_B;

    // ---- graph preprocessing + weight split ----
    prep_kernel<<<(n + 255) / 256, 256>>>(n);
    deg_kernel<<<(E + 255) / 256, 256>>>(dst, E);
    wtrans_kernel<<<(HDIM * 128 + 255) / 256, 256>>>(W1, w1h, w1l, 128, HDIM);
    wtrans_kernel<<<(HDIM * HDIM + 255) / 256, 256>>>(W2, w2h, w2l, HDIM, HDIM);
    rsqrt_kernel<<<(n + 255) / 256, 256>>>(n);
    scan1_kernel<<<nScanBlocks, SCAN_B>>>(n);
    scan2_kernel<<<1, 512>>>(nScanBlocks, n, E);
    scan3_kernel<<<nScanBlocks, SCAN_B>>>(n);
    scatter_kernel<<<(E + 255) / 256, 256>>>(src, dst, E);

    dim3 gemmGrid((n + 127) / 128, HDIM / 128);   // 391 x 2
    const int pullBlocks = (n + 7) / 8;

    // ---- layer 1 ----
    tgemm_kernel<<<gemmGrid, 256, SM_TOTAL>>>(x, w1h, w1l, t_ptr, n, 128);
    pull_kernel<<<pullBlocks, 256>>>(b1, n);

    // ---- layer 2 ----
    tgemm_kernel<<<gemmGrid, 256, SM_TOTAL>>>(y_ptr, w2h, w2l, t_ptr, n, HDIM);
    pull_kernel<<<pullBlocks, 256>>>(b2, n);

    // ---- mean pool + final linear ----
    colsum_kernel<<<592, HDIM>>>(n);
    final_kernel<<<1, HDIM>>>(Wl, bl, out, 1.0f / (float)n);
}

// round 5
// speedup vs baseline: 2.5341x; 1.1155x over previous
#include <cuda_runtime.h>
#include <cuda_bf16.h>
#include <cstddef>
#include <cstdint>

#define NMAX   50000
#define EMAX   800000
#define HDIM   256
#define H4     (HDIM / 4)
#define SCAN_B 256

// ---------------- scratch (device globals) ----------------
__device__ __align__(16) float g_t   [(size_t)NMAX * HDIM];
__device__ __align__(16) float g_y   [(size_t)NMAX * HDIM];
__device__ float g_dinv[NMAX];
__device__ int   g_degi[NMAX];
__device__ int   g_off [NMAX + 1];
__device__ int   g_cur [NMAX];
__device__ __align__(8) int2 g_epack[EMAX];   // {src, coef-as-int}
__device__ int   g_part[512];
__device__ float g_gv  [HDIM];
// bf16 split weights, transposed to [n][k]
__device__ __align__(16) __nv_bfloat16 g_w1t_hi[HDIM * 128];
__device__ __align__(16) __nv_bfloat16 g_w1t_lo[HDIM * 128];
__device__ __align__(16) __nv_bfloat16 g_w2t_hi[HDIM * HDIM];
__device__ __align__(16) __nv_bfloat16 g_w2t_lo[HDIM * HDIM];

// ---------------- helpers ----------------
__device__ __forceinline__ uint32_t smem_u32(const void* p) {
    uint32_t a;
    asm("{ .reg .u64 t; cvta.to.shared.u64 t, %1; cvt.u32.u64 %0, t; }" : "=r"(a) : "l"(p));
    return a;
}
#define SWZ(off) ((off) ^ (((off) >> 3) & 0x70))

__device__ __forceinline__ void ldsm_x4(uint32_t addr, uint32_t& r0, uint32_t& r1,
                                        uint32_t& r2, uint32_t& r3) {
    asm volatile("ldmatrix.sync.aligned.m8n8.x4.shared.b16 {%0,%1,%2,%3}, [%4];"
                 : "=r"(r0), "=r"(r1), "=r"(r2), "=r"(r3) : "r"(addr));
}

__device__ __forceinline__ void mma_bf16(float* d, const uint32_t* a, const uint32_t* b) {
    asm volatile("mma.sync.aligned.m16n8k16.row.col.f32.bf16.bf16.f32 "
                 "{%0,%1,%2,%3}, {%4,%5,%6,%7}, {%8,%9}, {%0,%1,%2,%3};"
                 : "+f"(d[0]), "+f"(d[1]), "+f"(d[2]), "+f"(d[3])
                 : "r"(a[0]), "r"(a[1]), "r"(a[2]), "r"(a[3]), "r"(b[0]), "r"(b[1]));
}

// ---------------- prep ----------------
__global__ void prep_kernel(int n)
{
    int i = blockIdx.x * blockDim.x + threadIdx.x;
    if (i < n)    g_degi[i] = 0;
    if (i < HDIM) g_gv[i]   = 0.0f;
}

__global__ void deg_kernel(const int* __restrict__ dst, int E)
{
    int e = blockIdx.x * blockDim.x + threadIdx.x;
    if (e < E) atomicAdd(&g_degi[dst[e]], 1);
}

__global__ void rsqrt_kernel(int n)
{
    int i = blockIdx.x * blockDim.x + threadIdx.x;
    if (i < n) g_dinv[i] = rsqrtf((float)g_degi[i] + 1.0f);
}

// ---------------- weight transpose + bf16 split: out[n*K+k] = W[k*N+n] ----------------
__global__ void wtrans_kernel(const float* __restrict__ W,
                              __nv_bfloat16* __restrict__ hi, __nv_bfloat16* __restrict__ lo,
                              int K, int N)
{
    int idx = blockIdx.x * 256 + threadIdx.x;
    if (idx >= N * K) return;
    int nn = idx / K, kk = idx - nn * K;
    float w = W[(size_t)kk * N + nn];
    __nv_bfloat16 h = __float2bfloat16_rn(w);
    float r = w - __bfloat162float(h);
    hi[idx] = h;
    lo[idx] = __float2bfloat16_rn(r);
}

// ---------------- scan ----------------
__global__ void scan1_kernel(int n)
{
    __shared__ int s[SCAN_B];
    int i = blockIdx.x * SCAN_B + threadIdx.x;
    s[threadIdx.x] = (i < n) ? g_degi[i] : 0;
    __syncthreads();
    for (int ofs = SCAN_B / 2; ofs > 0; ofs >>= 1) {
        if (threadIdx.x < ofs) s[threadIdx.x] += s[threadIdx.x + ofs];
        __syncthreads();
    }
    if (threadIdx.x == 0) g_part[blockIdx.x] = s[0];
}

__global__ void scan2_kernel(int nblocks, int n, int E)
{
    __shared__ int a[512], b[512];
    int t = threadIdx.x;
    int v = (t < nblocks) ? g_part[t] : 0;
    a[t] = v;
    __syncthreads();
    int* pin = a; int* pout = b;
    for (int ofs = 1; ofs < 512; ofs <<= 1) {
        pout[t] = (t >= ofs) ? pin[t] + pin[t - ofs] : pin[t];
        __syncthreads();
        int* tmp = pin; pin = pout; pout = tmp;
    }
    g_part[t] = (t == 0) ? 0 : pin[t - 1];
    if (t == 0) g_off[n] = E;
}

__global__ void scan3_kernel(int n)
{
    __shared__ int a[SCAN_B], b[SCAN_B];
    int t = threadIdx.x;
    int i = blockIdx.x * SCAN_B + t;
    int v = (i < n) ? g_degi[i] : 0;
    a[t] = v;
    __syncthreads();
    int* pin = a; int* pout = b;
    for (int ofs = 1; ofs < SCAN_B; ofs <<= 1) {
        pout[t] = (t >= ofs) ? pin[t] + pin[t - ofs] : pin[t];
        __syncthreads();
        int* tmp = pin; pin = pout; pout = tmp;
    }
    if (i < n) {
        int excl = (t == 0) ? 0 : pin[t - 1];
        int off = g_part[blockIdx.x] + excl;
        g_off[i] = off;
        g_cur[i] = off;
    }
}

// ---------------- scatter edges into CSR buckets with precomputed coef ----------------
__global__ void scatter_kernel(const int* __restrict__ src, const int* __restrict__ dst, int E)
{
    int e = blockIdx.x * blockDim.x + threadIdx.x;
    if (e < E) {
        int s = src[e];
        int d = dst[e];
        float coef = __ldg(&g_dinv[s]) * __ldg(&g_dinv[d]);
        int pos = atomicAdd(&g_cur[d], 1);
        g_epack[pos] = make_int2(s, __float_as_int(coef));
    }
}

// ---------------- HMMA GEMM: C[M,256] = A[M,K] @ W[K,256], split bf16 ----------------
// CTA 128x128, BK=64, 8 warps (warp tile 32x64). mma.sync m16n8k16 bf16, fp32 acc.
#define SA_HI 0
#define SA_LO 16384
#define SB_HI 32768
#define SB_LO 49152
#define SM_TOTAL 65536

__global__ __launch_bounds__(256, 2)
void tgemm_kernel(const float* __restrict__ A,
                  const __nv_bfloat16* __restrict__ WHI,
                  const __nv_bfloat16* __restrict__ WLO,
                  float* __restrict__ C, int M, int K)
{
    extern __shared__ char smem[];
    const uint32_t sb = smem_u32(smem);
    const int tid = threadIdx.x;
    const int wid = tid >> 5;
    const int lane = tid & 31;
    const int warp_m = wid & 3;     // 0..3 -> 32 rows each
    const int warp_n = wid >> 2;    // 0..1 -> 64 cols each
    const int row0 = blockIdx.x * 128;
    const int col0 = blockIdx.y * 128;

    float acc[2][8][4];
#pragma unroll
    for (int mt = 0; mt < 2; mt++)
#pragma unroll
        for (int nt = 0; nt < 8; nt++)
#pragma unroll
            for (int q = 0; q < 4; q++) acc[mt][nt][q] = 0.0f;

    const int lr   = lane & 7;
    const int lsel = lane >> 3;

    for (int k0 = 0; k0 < K; k0 += 64) {
        // ---- stage A [128 x 64 fp32] -> bf16 hi/lo into SW128 smem ----
#pragma unroll
        for (int i = 0; i < 8; i++) {
            const int idx = tid + (i << 8);
            const int row = idx >> 4;
            const int f   = idx & 15;
            const int grow = row0 + row;
            float4 a4 = make_float4(0.f, 0.f, 0.f, 0.f);
            if (grow < M)
                a4 = *reinterpret_cast<const float4*>(A + (size_t)grow * K + k0 + f * 4);
            __nv_bfloat16 h0 = __float2bfloat16_rn(a4.x);
            __nv_bfloat16 h1 = __float2bfloat16_rn(a4.y);
            __nv_bfloat16 h2 = __float2bfloat16_rn(a4.z);
            __nv_bfloat16 h3 = __float2bfloat16_rn(a4.w);
            __nv_bfloat16 l0 = __float2bfloat16_rn(a4.x - __bfloat162float(h0));
            __nv_bfloat16 l1 = __float2bfloat16_rn(a4.y - __bfloat162float(h1));
            __nv_bfloat16 l2 = __float2bfloat16_rn(a4.z - __bfloat162float(h2));
            __nv_bfloat16 l3 = __float2bfloat16_rn(a4.w - __bfloat162float(h3));
            __nv_bfloat162 ph0; ph0.x = h0; ph0.y = h1;
            __nv_bfloat162 ph1; ph1.x = h2; ph1.y = h3;
            __nv_bfloat162 pl0; pl0.x = l0; pl0.y = l1;
            __nv_bfloat162 pl1; pl1.x = l2; pl1.y = l3;
            uint2 uh, ul;
            uh.x = *reinterpret_cast<uint32_t*>(&ph0);
            uh.y = *reinterpret_cast<uint32_t*>(&ph1);
            ul.x = *reinterpret_cast<uint32_t*>(&pl0);
            ul.y = *reinterpret_cast<uint32_t*>(&pl1);
            const uint32_t sw = SWZ(row * 128 + f * 8);
            *reinterpret_cast<uint2*>(smem + SA_HI + sw) = uh;
            *reinterpret_cast<uint2*>(smem + SA_LO + sw) = ul;
        }
        // ---- stage B [128 n-rows x 64 k] hi/lo ----
#pragma unroll
        for (int i = 0; i < 4; i++) {
            const int idx = tid + (i << 8);
            const int nr = idx >> 3;
            const int u  = idx & 7;
            const uint32_t sw = SWZ(nr * 128 + u * 16);
            *reinterpret_cast<uint4*>(smem + SB_HI + sw) =
                *(reinterpret_cast<const uint4*>(WHI + (size_t)(col0 + nr) * K + k0) + u);
            *reinterpret_cast<uint4*>(smem + SB_LO + sw) =
                *(reinterpret_cast<const uint4*>(WLO + (size_t)(col0 + nr) * K + k0) + u);
        }
        __syncthreads();

        // ---- 4 x k16 steps ----
#pragma unroll
        for (int kk = 0; kk < 4; kk++) {
            const int kb = kk * 32 + (lsel & 2) * 8;
            uint32_t ah[8], al[8];
#pragma unroll
            for (int mt = 0; mt < 2; mt++) {
                const int arow = warp_m * 32 + mt * 16 + (lsel & 1) * 8 + lr;
                const uint32_t aoff = SWZ(arow * 128 + kb);
                ldsm_x4(sb + SA_HI + aoff, ah[mt*4+0], ah[mt*4+1], ah[mt*4+2], ah[mt*4+3]);
                ldsm_x4(sb + SA_LO + aoff, al[mt*4+0], al[mt*4+1], al[mt*4+2], al[mt*4+3]);
            }
            uint32_t bh[16], bl[16];
#pragma unroll
            for (int p = 0; p < 4; p++) {
                const int brow = warp_n * 64 + p * 16 + (lsel >> 1) * 8 + lr;
                const uint32_t boff = SWZ(brow * 128 + kk * 32 + (lsel & 1) * 16);
                ldsm_x4(sb + SB_HI + boff, bh[p*4+0], bh[p*4+1], bh[p*4+2], bh[p*4+3]);
                ldsm_x4(sb + SB_LO + boff, bl[p*4+0], bl[p*4+1], bl[p*4+2], bl[p*4+3]);
            }
#pragma unroll
            for (int mt = 0; mt < 2; mt++) {
#pragma unroll
                for (int nt = 0; nt < 8; nt++) {
                    mma_bf16(acc[mt][nt], &ah[mt*4], &bh[nt*2]);
                    mma_bf16(acc[mt][nt], &al[mt*4], &bh[nt*2]);
                    mma_bf16(acc[mt][nt], &ah[mt*4], &bl[nt*2]);
                }
            }
        }
        __syncthreads();
    }

    // ---- epilogue: direct register stores ----
    const int tr = lane >> 2;
    const int tc = (lane & 3) * 2;
#pragma unroll
    for (int mt = 0; mt < 2; mt++) {
#pragma unroll
        for (int nt = 0; nt < 8; nt++) {
            const int col = col0 + warp_n * 64 + nt * 8 + tc;
            const int r0 = row0 + warp_m * 32 + mt * 16 + tr;
            if (r0 < M) {
                float2 v; v.x = acc[mt][nt][0]; v.y = acc[mt][nt][1];
                *reinterpret_cast<float2*>(C + (size_t)r0 * HDIM + col) = v;
            }
            if (r0 + 8 < M) {
                float2 v; v.x = acc[mt][nt][2]; v.y = acc[mt][nt][3];
                *reinterpret_cast<float2*>(C + (size_t)(r0 + 8) * HDIM + col) = v;
            }
        }
    }
}

// ---------------- pull aggregation + finalize (v2: 2 warps/node, no shfl) ----------------
// y[d] = relu( sum_e coef_e * t[src_e]  +  t[d]*dinv[d]^2  +  b )
__global__ __launch_bounds__(256)
void pull_kernel(const float* __restrict__ b, int n)
{
    const int wid  = threadIdx.x >> 5;
    const int lane = threadIdx.x & 31;
    const int d    = blockIdx.x * 4 + (wid >> 1);
    if (d >= n) return;
    const int half = wid & 1;
    const int cf4  = half * 32 + lane;          // float4 column index 0..63

    const int beg = g_off[d];
    const int end = g_off[d + 1];

    const float4* __restrict__ T = reinterpret_cast<const float4*>(g_t);
    const int2*   __restrict__ P = g_epack;

    float4 acc = make_float4(0.f, 0.f, 0.f, 0.f);

    int e = beg;
#pragma unroll 1
    for (; e + 4 <= end; e += 4) {
        int2 p0 = __ldg(P + e + 0);
        int2 p1 = __ldg(P + e + 1);
        int2 p2 = __ldg(P + e + 2);
        int2 p3 = __ldg(P + e + 3);
        float4 v0 = __ldg(T + (size_t)p0.x * H4 + cf4);
        float4 v1 = __ldg(T + (size_t)p1.x * H4 + cf4);
        float4 v2 = __ldg(T + (size_t)p2.x * H4 + cf4);
        float4 v3 = __ldg(T + (size_t)p3.x * H4 + cf4);
        const float c0 = __int_as_float(p0.y);
        const float c1 = __int_as_float(p1.y);
        const float c2 = __int_as_float(p2.y);
        const float c3 = __int_as_float(p3.y);
        acc.x = fmaf(c0, v0.x, acc.x); acc.y = fmaf(c0, v0.y, acc.y);
        acc.z = fmaf(c0, v0.z, acc.z); acc.w = fmaf(c0, v0.w, acc.w);
        acc.x = fmaf(c1, v1.x, acc.x); acc.y = fmaf(c1, v1.y, acc.y);
        acc.z = fmaf(c1, v1.z, acc.z); acc.w = fmaf(c1, v1.w, acc.w);
        acc.x = fmaf(c2, v2.x, acc.x); acc.y = fmaf(c2, v2.y, acc.y);
        acc.z = fmaf(c2, v2.z, acc.z); acc.w = fmaf(c2, v2.w, acc.w);
        acc.x = fmaf(c3, v3.x, acc.x); acc.y = fmaf(c3, v3.y, acc.y);
        acc.z = fmaf(c3, v3.z, acc.z); acc.w = fmaf(c3, v3.w, acc.w);
    }
    for (; e < end; e++) {
        int2 p = __ldg(P + e);
        float4 v = __ldg(T + (size_t)p.x * H4 + cf4);
        const float c = __int_as_float(p.y);
        acc.x = fmaf(c, v.x, acc.x); acc.y = fmaf(c, v.y, acc.y);
        acc.z = fmaf(c, v.z, acc.z); acc.w = fmaf(c, v.w, acc.w);
    }

    const float dd = g_dinv[d];
    const float d2 = dd * dd;
    float4 hv = __ldg(T + (size_t)d * H4 + cf4);
    float4 bv = __ldg(reinterpret_cast<const float4*>(b) + cf4);

    float4 r;
    r.x = fmaxf(fmaf(d2, hv.x, acc.x) + bv.x, 0.0f);
    r.y = fmaxf(fmaf(d2, hv.y, acc.y) + bv.y, 0.0f);
    r.z = fmaxf(fmaf(d2, hv.z, acc.z) + bv.z, 0.0f);
    r.w = fmaxf(fmaf(d2, hv.w, acc.w) + bv.w, 0.0f);

    reinterpret_cast<float4*>(g_y)[(size_t)d * H4 + cf4] = r;
}

// ---------------- column sums ----------------
__global__ void colsum_kernel(int n)
{
    const int j = threadIdx.x;
    float s = 0.0f;
    for (int r = blockIdx.x; r < n; r += gridDim.x)
        s += g_y[(size_t)r * HDIM + j];
    atomicAdd(&g_gv[j], s);
}

// ---------------- final linear ----------------
__global__ void final_kernel(const float* __restrict__ Wl, const float* __restrict__ bl,
                             float* __restrict__ out, float invN)
{
    __shared__ float s[2];
    if (threadIdx.x < 2) s[threadIdx.x] = 0.0f;
    __syncthreads();
    const int j = threadIdx.x;
    const float gj = g_gv[j] * invN;
    atomicAdd(&s[0], gj * Wl[j * 2 + 0]);
    atomicAdd(&s[1], gj * Wl[j * 2 + 1]);
    __syncthreads();
    if (threadIdx.x < 2) out[threadIdx.x] = s[threadIdx.x] + bl[threadIdx.x];
}

// ---------------- launcher ----------------
extern "C" void kernel_launch(void* const* d_in, const int* in_sizes, int n_in,
                              void* d_out, int out_size)
{
    const float* x  = (const float*)d_in[0];
    const int*   ei = (const int*)  d_in[1];
    const float* W1 = (const float*)d_in[3];
    const float* b1 = (const float*)d_in[4];
    const float* W2 = (const float*)d_in[5];
    const float* b2 = (const float*)d_in[6];
    const float* Wl = (const float*)d_in[7];
    const float* bl = (const float*)d_in[8];
    float* out = (float*)d_out;

    const int n = in_sizes[0] / 128;   // 50000
    const int E = in_sizes[1] / 2;     // 800000

    const int* src = ei;
    const int* dst = ei + E;

    float* t_ptr;  cudaGetSymbolAddress((void**)&t_ptr,  g_t);
    float* y_ptr;  cudaGetSymbolAddress((void**)&y_ptr,  g_y);
    __nv_bfloat16 *w1h, *w1l, *w2h, *w2l;
    cudaGetSymbolAddress((void**)&w1h, g_w1t_hi);
    cudaGetSymbolAddress((void**)&w1l, g_w1t_lo);
    cudaGetSymbolAddress((void**)&w2h, g_w2t_hi);
    cudaGetSymbolAddress((void**)&w2l, g_w2t_lo);

    cudaFuncSetAttribute(tgemm_kernel, cudaFuncAttributeMaxDynamicSharedMemorySize, SM_TOTAL);

    const int nScanBlocks = (n + SCAN_B - 1) / SCAN_B;

    // ---- graph preprocessing + weight split ----
    prep_kernel<<<(n + 255) / 256, 256>>>(n);
    deg_kernel<<<(E + 255) / 256, 256>>>(dst, E);
    wtrans_kernel<<<(HDIM * 128 + 255) / 256, 256>>>(W1, w1h, w1l, 128, HDIM);
    wtrans_kernel<<<(HDIM * HDIM + 255) / 256, 256>>>(W2, w2h, w2l, HDIM, HDIM);
    rsqrt_kernel<<<(n + 255) / 256, 256>>>(n);
    scan1_kernel<<<nScanBlocks, SCAN_B>>>(n);
    scan2_kernel<<<1, 512>>>(nScanBlocks, n, E);
    scan3_kernel<<<nScanBlocks, SCAN_B>>>(n);
    scatter_kernel<<<(E + 255) / 256, 256>>>(src, dst, E);

    dim3 gemmGrid((n + 127) / 128, HDIM / 128);   // 391 x 2
    const int pullBlocks = (n + 3) / 4;            // 12500

    // ---- layer 1 ----
    tgemm_kernel<<<gemmGrid, 256, SM_TOTAL>>>(x, w1h, w1l, t_ptr, n, 128);
    pull_kernel<<<pullBlocks, 256>>>(b1, n);

    // ---- layer 2 ----
    tgemm_kernel<<<gemmGrid, 256, SM_TOTAL>>>(y_ptr, w2h, w2l, t_ptr, n, HDIM);
    pull_kernel<<<pullBlocks, 256>>>(b2, n);

    // ---- mean pool + final linear ----
    colsum_kernel<<<592, HDIM>>>(n);
    final_kernel<<<1, HDIM>>>(Wl, bl, out, 1.0f / (float)n);
}

// round 6
// speedup vs baseline: 3.1670x; 1.2497x over previous
#include <cuda_runtime.h>
#include <cuda_bf16.h>
#include <cstddef>
#include <cstdint>

#define NMAX   50000
#define EMAX   800000
#define HDIM   256
#define H4     (HDIM / 4)
#define SCAN_B 256

// ---------------- scratch (device globals) ----------------
__device__ __align__(16) __nv_bfloat16 g_tb[(size_t)NMAX * HDIM];  // GEMM output (bf16 messages)
__device__ __align__(16) float g_y   [(size_t)NMAX * HDIM];        // layer activations (fp32)
__device__ float g_dinv[NMAX];
__device__ int   g_degi[NMAX];
__device__ int   g_off [NMAX + 1];
__device__ int   g_cur [NMAX];
__device__ __align__(8) int2 g_epack[EMAX];   // {src, coef-as-int}
__device__ int   g_part[512];
__device__ float g_gv  [HDIM];
// bf16 split weights, transposed to [n][k]
__device__ __align__(16) __nv_bfloat16 g_w1t_hi[HDIM * 128];
__device__ __align__(16) __nv_bfloat16 g_w1t_lo[HDIM * 128];
__device__ __align__(16) __nv_bfloat16 g_w2t_hi[HDIM * HDIM];
__device__ __align__(16) __nv_bfloat16 g_w2t_lo[HDIM * HDIM];

// ---------------- helpers ----------------
__device__ __forceinline__ uint32_t smem_u32(const void* p) {
    uint32_t a;
    asm("{ .reg .u64 t; cvta.to.shared.u64 t, %1; cvt.u32.u64 %0, t; }" : "=r"(a) : "l"(p));
    return a;
}
#define SWZ(off) ((off) ^ (((off) >> 3) & 0x70))

__device__ __forceinline__ void ldsm_x4(uint32_t addr, uint32_t& r0, uint32_t& r1,
                                        uint32_t& r2, uint32_t& r3) {
    asm volatile("ldmatrix.sync.aligned.m8n8.x4.shared.b16 {%0,%1,%2,%3}, [%4];"
                 : "=r"(r0), "=r"(r1), "=r"(r2), "=r"(r3) : "r"(addr));
}

__device__ __forceinline__ void mma_bf16(float* d, const uint32_t* a, const uint32_t* b) {
    asm volatile("mma.sync.aligned.m16n8k16.row.col.f32.bf16.bf16.f32 "
                 "{%0,%1,%2,%3}, {%4,%5,%6,%7}, {%8,%9}, {%0,%1,%2,%3};"
                 : "+f"(d[0]), "+f"(d[1]), "+f"(d[2]), "+f"(d[3])
                 : "r"(a[0]), "r"(a[1]), "r"(a[2]), "r"(a[3]), "r"(b[0]), "r"(b[1]));
}

// bf16x8 (uint4) -> 8x fma into acc
__device__ __forceinline__ void acc8(float* acc, uint4 v, float c) {
    float2 f0 = __bfloat1622float2(*reinterpret_cast<__nv_bfloat162*>(&v.x));
    float2 f1 = __bfloat1622float2(*reinterpret_cast<__nv_bfloat162*>(&v.y));
    float2 f2 = __bfloat1622float2(*reinterpret_cast<__nv_bfloat162*>(&v.z));
    float2 f3 = __bfloat1622float2(*reinterpret_cast<__nv_bfloat162*>(&v.w));
    acc[0] = fmaf(c, f0.x, acc[0]); acc[1] = fmaf(c, f0.y, acc[1]);
    acc[2] = fmaf(c, f1.x, acc[2]); acc[3] = fmaf(c, f1.y, acc[3]);
    acc[4] = fmaf(c, f2.x, acc[4]); acc[5] = fmaf(c, f2.y, acc[5]);
    acc[6] = fmaf(c, f3.x, acc[6]); acc[7] = fmaf(c, f3.y, acc[7]);
}

// ---------------- prep ----------------
__global__ void prep_kernel(int n)
{
    int i = blockIdx.x * blockDim.x + threadIdx.x;
    if (i < n)    g_degi[i] = 0;
    if (i < HDIM) g_gv[i]   = 0.0f;
}

__global__ void deg_kernel(const int* __restrict__ dst, int E)
{
    int e = blockIdx.x * blockDim.x + threadIdx.x;
    if (e < E) atomicAdd(&g_degi[dst[e]], 1);
}

__global__ void rsqrt_kernel(int n)
{
    int i = blockIdx.x * blockDim.x + threadIdx.x;
    if (i < n) g_dinv[i] = rsqrtf((float)g_degi[i] + 1.0f);
}

// ---------------- weight transpose + bf16 split ----------------
__global__ void wtrans_kernel(const float* __restrict__ W,
                              __nv_bfloat16* __restrict__ hi, __nv_bfloat16* __restrict__ lo,
                              int K, int N)
{
    int idx = blockIdx.x * 256 + threadIdx.x;
    if (idx >= N * K) return;
    int nn = idx / K, kk = idx - nn * K;
    float w = W[(size_t)kk * N + nn];
    __nv_bfloat16 h = __float2bfloat16_rn(w);
    float r = w - __bfloat162float(h);
    hi[idx] = h;
    lo[idx] = __float2bfloat16_rn(r);
}

// ---------------- scan ----------------
__global__ void scan1_kernel(int n)
{
    __shared__ int s[SCAN_B];
    int i = blockIdx.x * SCAN_B + threadIdx.x;
    s[threadIdx.x] = (i < n) ? g_degi[i] : 0;
    __syncthreads();
    for (int ofs = SCAN_B / 2; ofs > 0; ofs >>= 1) {
        if (threadIdx.x < ofs) s[threadIdx.x] += s[threadIdx.x + ofs];
        __syncthreads();
    }
    if (threadIdx.x == 0) g_part[blockIdx.x] = s[0];
}

__global__ void scan2_kernel(int nblocks, int n, int E)
{
    __shared__ int a[512], b[512];
    int t = threadIdx.x;
    int v = (t < nblocks) ? g_part[t] : 0;
    a[t] = v;
    __syncthreads();
    int* pin = a; int* pout = b;
    for (int ofs = 1; ofs < 512; ofs <<= 1) {
        pout[t] = (t >= ofs) ? pin[t] + pin[t - ofs] : pin[t];
        __syncthreads();
        int* tmp = pin; pin = pout; pout = tmp;
    }
    g_part[t] = (t == 0) ? 0 : pin[t - 1];
    if (t == 0) g_off[n] = E;
}

__global__ void scan3_kernel(int n)
{
    __shared__ int a[SCAN_B], b[SCAN_B];
    int t = threadIdx.x;
    int i = blockIdx.x * SCAN_B + t;
    int v = (i < n) ? g_degi[i] : 0;
    a[t] = v;
    __syncthreads();
    int* pin = a; int* pout = b;
    for (int ofs = 1; ofs < SCAN_B; ofs <<= 1) {
        pout[t] = (t >= ofs) ? pin[t] + pin[t - ofs] : pin[t];
        __syncthreads();
        int* tmp = pin; pin = pout; pout = tmp;
    }
    if (i < n) {
        int excl = (t == 0) ? 0 : pin[t - 1];
        int off = g_part[blockIdx.x] + excl;
        g_off[i] = off;
        g_cur[i] = off;
    }
}

// ---------------- scatter edges into CSR buckets with precomputed coef ----------------
__global__ void scatter_kernel(const int* __restrict__ src, const int* __restrict__ dst, int E)
{
    int e = blockIdx.x * blockDim.x + threadIdx.x;
    if (e < E) {
        int s = src[e];
        int d = dst[e];
        float coef = __ldg(&g_dinv[s]) * __ldg(&g_dinv[d]);
        int pos = atomicAdd(&g_cur[d], 1);
        g_epack[pos] = make_int2(s, __float_as_int(coef));
    }
}

// ---------------- HMMA GEMM: C_bf16[M,256] = A[M,K] @ W[K,256], split bf16 ----------------
#define SA_HI 0
#define SA_LO 16384
#define SB_HI 32768
#define SB_LO 49152
#define SM_TOTAL 65536

__global__ __launch_bounds__(256, 2)
void tgemm_kernel(const float* __restrict__ A,
                  const __nv_bfloat16* __restrict__ WHI,
                  const __nv_bfloat16* __restrict__ WLO,
                  __nv_bfloat16* __restrict__ C, int M, int K)
{
    extern __shared__ char smem[];
    const uint32_t sb = smem_u32(smem);
    const int tid = threadIdx.x;
    const int wid = tid >> 5;
    const int lane = tid & 31;
    const int warp_m = wid & 3;
    const int warp_n = wid >> 2;
    const int row0 = blockIdx.x * 128;
    const int col0 = blockIdx.y * 128;

    float acc[2][8][4];
#pragma unroll
    for (int mt = 0; mt < 2; mt++)
#pragma unroll
        for (int nt = 0; nt < 8; nt++)
#pragma unroll
            for (int q = 0; q < 4; q++) acc[mt][nt][q] = 0.0f;

    const int lr   = lane & 7;
    const int lsel = lane >> 3;

    for (int k0 = 0; k0 < K; k0 += 64) {
        // ---- stage A [128 x 64 fp32] -> bf16 hi/lo into SW128 smem ----
#pragma unroll
        for (int i = 0; i < 8; i++) {
            const int idx = tid + (i << 8);
            const int row = idx >> 4;
            const int f   = idx & 15;
            const int grow = row0 + row;
            float4 a4 = make_float4(0.f, 0.f, 0.f, 0.f);
            if (grow < M)
                a4 = *reinterpret_cast<const float4*>(A + (size_t)grow * K + k0 + f * 4);
            __nv_bfloat16 h0 = __float2bfloat16_rn(a4.x);
            __nv_bfloat16 h1 = __float2bfloat16_rn(a4.y);
            __nv_bfloat16 h2 = __float2bfloat16_rn(a4.z);
            __nv_bfloat16 h3 = __float2bfloat16_rn(a4.w);
            __nv_bfloat16 l0 = __float2bfloat16_rn(a4.x - __bfloat162float(h0));
            __nv_bfloat16 l1 = __float2bfloat16_rn(a4.y - __bfloat162float(h1));
            __nv_bfloat16 l2 = __float2bfloat16_rn(a4.z - __bfloat162float(h2));
            __nv_bfloat16 l3 = __float2bfloat16_rn(a4.w - __bfloat162float(h3));
            __nv_bfloat162 ph0; ph0.x = h0; ph0.y = h1;
            __nv_bfloat162 ph1; ph1.x = h2; ph1.y = h3;
            __nv_bfloat162 pl0; pl0.x = l0; pl0.y = l1;
            __nv_bfloat162 pl1; pl1.x = l2; pl1.y = l3;
            uint2 uh, ul;
            uh.x = *reinterpret_cast<uint32_t*>(&ph0);
            uh.y = *reinterpret_cast<uint32_t*>(&ph1);
            ul.x = *reinterpret_cast<uint32_t*>(&pl0);
            ul.y = *reinterpret_cast<uint32_t*>(&pl1);
            const uint32_t sw = SWZ(row * 128 + f * 8);
            *reinterpret_cast<uint2*>(smem + SA_HI + sw) = uh;
            *reinterpret_cast<uint2*>(smem + SA_LO + sw) = ul;
        }
        // ---- stage B [128 n-rows x 64 k] hi/lo ----
#pragma unroll
        for (int i = 0; i < 4; i++) {
            const int idx = tid + (i << 8);
            const int nr = idx >> 3;
            const int u  = idx & 7;
            const uint32_t sw = SWZ(nr * 128 + u * 16);
            *reinterpret_cast<uint4*>(smem + SB_HI + sw) =
                *(reinterpret_cast<const uint4*>(WHI + (size_t)(col0 + nr) * K + k0) + u);
            *reinterpret_cast<uint4*>(smem + SB_LO + sw) =
                *(reinterpret_cast<const uint4*>(WLO + (size_t)(col0 + nr) * K + k0) + u);
        }
        __syncthreads();

        // ---- 4 x k16 steps ----
#pragma unroll
        for (int kk = 0; kk < 4; kk++) {
            const int kb = kk * 32 + (lsel & 2) * 8;
            uint32_t ah[8], al[8];
#pragma unroll
            for (int mt = 0; mt < 2; mt++) {
                const int arow = warp_m * 32 + mt * 16 + (lsel & 1) * 8 + lr;
                const uint32_t aoff = SWZ(arow * 128 + kb);
                ldsm_x4(sb + SA_HI + aoff, ah[mt*4+0], ah[mt*4+1], ah[mt*4+2], ah[mt*4+3]);
                ldsm_x4(sb + SA_LO + aoff, al[mt*4+0], al[mt*4+1], al[mt*4+2], al[mt*4+3]);
            }
            uint32_t bh[16], bl[16];
#pragma unroll
            for (int p = 0; p < 4; p++) {
                const int brow = warp_n * 64 + p * 16 + (lsel >> 1) * 8 + lr;
                const uint32_t boff = SWZ(brow * 128 + kk * 32 + (lsel & 1) * 16);
                ldsm_x4(sb + SB_HI + boff, bh[p*4+0], bh[p*4+1], bh[p*4+2], bh[p*4+3]);
                ldsm_x4(sb + SB_LO + boff, bl[p*4+0], bl[p*4+1], bl[p*4+2], bl[p*4+3]);
            }
#pragma unroll
            for (int mt = 0; mt < 2; mt++) {
#pragma unroll
                for (int nt = 0; nt < 8; nt++) {
                    mma_bf16(acc[mt][nt], &ah[mt*4], &bh[nt*2]);
                    mma_bf16(acc[mt][nt], &al[mt*4], &bh[nt*2]);
                    mma_bf16(acc[mt][nt], &ah[mt*4], &bl[nt*2]);
                }
            }
        }
        __syncthreads();
    }

    // ---- epilogue: direct bf16 stores ----
    const int tr = lane >> 2;
    const int tc = (lane & 3) * 2;
#pragma unroll
    for (int mt = 0; mt < 2; mt++) {
#pragma unroll
        for (int nt = 0; nt < 8; nt++) {
            const int col = col0 + warp_n * 64 + nt * 8 + tc;
            const int r0 = row0 + warp_m * 32 + mt * 16 + tr;
            if (r0 < M) {
                __nv_bfloat162 v = __float22bfloat162_rn(make_float2(acc[mt][nt][0], acc[mt][nt][1]));
                *reinterpret_cast<__nv_bfloat162*>(C + (size_t)r0 * HDIM + col) = v;
            }
            if (r0 + 8 < M) {
                __nv_bfloat162 v = __float22bfloat162_rn(make_float2(acc[mt][nt][2], acc[mt][nt][3]));
                *reinterpret_cast<__nv_bfloat162*>(C + (size_t)(r0 + 8) * HDIM + col) = v;
            }
        }
    }
}

// ---------------- pull aggregation + finalize (v3: 1 warp/node, bf16 messages) ----------------
// y[d] = relu( sum_e coef_e * tb[src_e]  +  tb[d]*dinv[d]^2  +  b )
__global__ __launch_bounds__(256)
void pull_kernel(const float* __restrict__ b, int n)
{
    const int wid  = threadIdx.x >> 5;
    const int lane = threadIdx.x & 31;
    const int d    = blockIdx.x * 8 + wid;
    if (d >= n) return;

    const int beg = g_off[d];
    const int end = g_off[d + 1];

    const uint4* __restrict__ T = reinterpret_cast<const uint4*>(g_tb);  // 32 uint4 per row
    const int2*  __restrict__ P = g_epack;

    float acc[8] = {0.f, 0.f, 0.f, 0.f, 0.f, 0.f, 0.f, 0.f};

    int e = beg;
#pragma unroll 1
    for (; e + 4 <= end; e += 4) {
        int2 p0 = __ldg(P + e + 0);
        int2 p1 = __ldg(P + e + 1);
        int2 p2 = __ldg(P + e + 2);
        int2 p3 = __ldg(P + e + 3);
        uint4 v0 = __ldg(T + (size_t)p0.x * 32 + lane);
        uint4 v1 = __ldg(T + (size_t)p1.x * 32 + lane);
        uint4 v2 = __ldg(T + (size_t)p2.x * 32 + lane);
        uint4 v3 = __ldg(T + (size_t)p3.x * 32 + lane);
        acc8(acc, v0, __int_as_float(p0.y));
        acc8(acc, v1, __int_as_float(p1.y));
        acc8(acc, v2, __int_as_float(p2.y));
        acc8(acc, v3, __int_as_float(p3.y));
    }
    for (; e < end; e++) {
        int2 p = __ldg(P + e);
        uint4 v = __ldg(T + (size_t)p.x * 32 + lane);
        acc8(acc, v, __int_as_float(p.y));
    }

    // self-loop term
    const float dd = g_dinv[d];
    acc8(acc, __ldg(T + (size_t)d * 32 + lane), dd * dd);

    // bias + relu + store fp32
    const float4* bp = reinterpret_cast<const float4*>(b) + lane * 2;
    float4 b0 = __ldg(bp);
    float4 b1 = __ldg(bp + 1);
    float4 r0, r1;
    r0.x = fmaxf(acc[0] + b0.x, 0.0f);
    r0.y = fmaxf(acc[1] + b0.y, 0.0f);
    r0.z = fmaxf(acc[2] + b0.z, 0.0f);
    r0.w = fmaxf(acc[3] + b0.w, 0.0f);
    r1.x = fmaxf(acc[4] + b1.x, 0.0f);
    r1.y = fmaxf(acc[5] + b1.y, 0.0f);
    r1.z = fmaxf(acc[6] + b1.z, 0.0f);
    r1.w = fmaxf(acc[7] + b1.w, 0.0f);

    float4* yp = reinterpret_cast<float4*>(g_y) + (size_t)d * H4 + lane * 2;
    yp[0] = r0;
    yp[1] = r1;
}

// ---------------- column sums ----------------
__global__ void colsum_kernel(int n)
{
    const int j = threadIdx.x;
    float s = 0.0f;
    for (int r = blockIdx.x; r < n; r += gridDim.x)
        s += g_y[(size_t)r * HDIM + j];
    atomicAdd(&g_gv[j], s);
}

// ---------------- final linear ----------------
__global__ void final_kernel(const float* __restrict__ Wl, const float* __restrict__ bl,
                             float* __restrict__ out, float invN)
{
    __shared__ float s[2];
    if (threadIdx.x < 2) s[threadIdx.x] = 0.0f;
    __syncthreads();
    const int j = threadIdx.x;
    const float gj = g_gv[j] * invN;
    atomicAdd(&s[0], gj * Wl[j * 2 + 0]);
    atomicAdd(&s[1], gj * Wl[j * 2 + 1]);
    __syncthreads();
    if (threadIdx.x < 2) out[threadIdx.x] = s[threadIdx.x] + bl[threadIdx.x];
}

// ---------------- launcher ----------------
extern "C" void kernel_launch(void* const* d_in, const int* in_sizes, int n_in,
                              void* d_out, int out_size)
{
    const float* x  = (const float*)d_in[0];
    const int*   ei = (const int*)  d_in[1];
    const float* W1 = (const float*)d_in[3];
    const float* b1 = (const float*)d_in[4];
    const float* W2 = (const float*)d_in[5];
    const float* b2 = (const float*)d_in[6];
    const float* Wl = (const float*)d_in[7];
    const float* bl = (const float*)d_in[8];
    float* out = (float*)d_out;

    const int n = in_sizes[0] / 128;   // 50000
    const int E = in_sizes[1] / 2;     // 800000

    const int* src = ei;
    const int* dst = ei + E;

    __nv_bfloat16* tb_ptr; cudaGetSymbolAddress((void**)&tb_ptr, g_tb);
    float* y_ptr;  cudaGetSymbolAddress((void**)&y_ptr,  g_y);
    __nv_bfloat16 *w1h, *w1l, *w2h, *w2l;
    cudaGetSymbolAddress((void**)&w1h, g_w1t_hi);
    cudaGetSymbolAddress((void**)&w1l, g_w1t_lo);
    cudaGetSymbolAddress((void**)&w2h, g_w2t_hi);
    cudaGetSymbolAddress((void**)&w2l, g_w2t_lo);

    cudaFuncSetAttribute(tgemm_kernel, cudaFuncAttributeMaxDynamicSharedMemorySize, SM_TOTAL);

    const int nScanBlocks = (n + SCAN_B - 1) / SCAN_B;

    // ---- graph preprocessing + weight split ----
    prep_kernel<<<(n + 255) / 256, 256>>>(n);
    deg_kernel<<<(E + 255) / 256, 256>>>(dst, E);
    wtrans_kernel<<<(HDIM * 128 + 255) / 256, 256>>>(W1, w1h, w1l, 128, HDIM);
    wtrans_kernel<<<(HDIM * HDIM + 255) / 256, 256>>>(W2, w2h, w2l, HDIM, HDIM);
    rsqrt_kernel<<<(n + 255) / 256, 256>>>(n);
    scan1_kernel<<<nScanBlocks, SCAN_B>>>(n);
    scan2_kernel<<<1, 512>>>(nScanBlocks, n, E);
    scan3_kernel<<<nScanBlocks, SCAN_B>>>(n);
    scatter_kernel<<<(E + 255) / 256, 256>>>(src, dst, E);

    dim3 gemmGrid((n + 127) / 128, HDIM / 128);   // 391 x 2
    const int pullBlocks = (n + 7) / 8;            // 6250

    // ---- layer 1 ----
    tgemm_kernel<<<gemmGrid, 256, SM_TOTAL>>>(x, w1h, w1l, tb_ptr, n, 128);
    pull_kernel<<<pullBlocks, 256>>>(b1, n);

    // ---- layer 2 ----
    tgemm_kernel<<<gemmGrid, 256, SM_TOTAL>>>(y_ptr, w2h, w2l, tb_ptr, n, HDIM);
    pull_kernel<<<pullBlocks, 256>>>(b2, n);

    // ---- mean pool + final linear ----
    colsum_kernel<<<592, HDIM>>>(n);
    final_kernel<<<1, HDIM>>>(Wl, bl, out, 1.0f / (float)n);
}

// round 7
// speedup vs baseline: 3.3271x; 1.0505x over previous
#include <cuda_runtime.h>
#include <cuda_bf16.h>
#include <cstddef>
#include <cstdint>

#define NMAX   50000
#define EMAX   800000
#define HDIM   256
#define H4     (HDIM / 4)
#define SCAN_B 256

// ---------------- scratch (device globals) ----------------
__device__ __align__(16) __nv_bfloat16 g_tb[(size_t)NMAX * HDIM];  // GEMM output (bf16 messages)
__device__ __align__(16) float g_y   [(size_t)NMAX * HDIM];        // layer activations (fp32)
__device__ float g_dinv[NMAX];
__device__ int   g_degi[NMAX];
__device__ int   g_off [NMAX + 1];
__device__ int   g_cur [NMAX];
__device__ __align__(8) int2 g_epack[EMAX];   // {src, coef-as-int}
__device__ int   g_part[512];
__device__ float g_gv  [HDIM];
// bf16 split weights, transposed to [n][k]
__device__ __align__(16) __nv_bfloat16 g_w1t_hi[HDIM * 128];
__device__ __align__(16) __nv_bfloat16 g_w1t_lo[HDIM * 128];
__device__ __align__(16) __nv_bfloat16 g_w2t_hi[HDIM * HDIM];
__device__ __align__(16) __nv_bfloat16 g_w2t_lo[HDIM * HDIM];

// ---------------- helpers ----------------
__device__ __forceinline__ uint32_t smem_u32(const void* p) {
    uint32_t a;
    asm("{ .reg .u64 t; cvta.to.shared.u64 t, %1; cvt.u32.u64 %0, t; }" : "=r"(a) : "l"(p));
    return a;
}
#define SWZ(off) ((off) ^ (((off) >> 3) & 0x70))

__device__ __forceinline__ void ldsm_x4(uint32_t addr, uint32_t& r0, uint32_t& r1,
                                        uint32_t& r2, uint32_t& r3) {
    asm volatile("ldmatrix.sync.aligned.m8n8.x4.shared.b16 {%0,%1,%2,%3}, [%4];"
                 : "=r"(r0), "=r"(r1), "=r"(r2), "=r"(r3) : "r"(addr));
}

__device__ __forceinline__ void mma_bf16(float* d, const uint32_t* a, const uint32_t* b) {
    asm volatile("mma.sync.aligned.m16n8k16.row.col.f32.bf16.bf16.f32 "
                 "{%0,%1,%2,%3}, {%4,%5,%6,%7}, {%8,%9}, {%0,%1,%2,%3};"
                 : "+f"(d[0]), "+f"(d[1]), "+f"(d[2]), "+f"(d[3])
                 : "r"(a[0]), "r"(a[1]), "r"(a[2]), "r"(a[3]), "r"(b[0]), "r"(b[1]));
}

// bf16x8 (uint4) -> 8x fma into acc
__device__ __forceinline__ void acc8(float* acc, uint4 v, float c) {
    float2 f0 = __bfloat1622float2(*reinterpret_cast<__nv_bfloat162*>(&v.x));
    float2 f1 = __bfloat1622float2(*reinterpret_cast<__nv_bfloat162*>(&v.y));
    float2 f2 = __bfloat1622float2(*reinterpret_cast<__nv_bfloat162*>(&v.z));
    float2 f3 = __bfloat1622float2(*reinterpret_cast<__nv_bfloat162*>(&v.w));
    acc[0] = fmaf(c, f0.x, acc[0]); acc[1] = fmaf(c, f0.y, acc[1]);
    acc[2] = fmaf(c, f1.x, acc[2]); acc[3] = fmaf(c, f1.y, acc[3]);
    acc[4] = fmaf(c, f2.x, acc[4]); acc[5] = fmaf(c, f2.y, acc[5]);
    acc[6] = fmaf(c, f3.x, acc[6]); acc[7] = fmaf(c, f3.y, acc[7]);
}

// ---------------- prep ----------------
__global__ void prep_kernel(int n)
{
    int i = blockIdx.x * blockDim.x + threadIdx.x;
    if (i < n)    g_degi[i] = 0;
    if (i < HDIM) g_gv[i]   = 0.0f;
}

__global__ void deg_kernel(const int* __restrict__ dst, int E)
{
    int e = blockIdx.x * blockDim.x + threadIdx.x;
    if (e < E) atomicAdd(&g_degi[dst[e]], 1);
}

__global__ void rsqrt_kernel(int n)
{
    int i = blockIdx.x * blockDim.x + threadIdx.x;
    if (i < n) g_dinv[i] = rsqrtf((float)g_degi[i] + 1.0f);
}

// ---------------- weight transpose + bf16 split ----------------
__global__ void wtrans_kernel(const float* __restrict__ W,
                              __nv_bfloat16* __restrict__ hi, __nv_bfloat16* __restrict__ lo,
                              int K, int N)
{
    int idx = blockIdx.x * 256 + threadIdx.x;
    if (idx >= N * K) return;
    int nn = idx / K, kk = idx - nn * K;
    float w = W[(size_t)kk * N + nn];
    __nv_bfloat16 h = __float2bfloat16_rn(w);
    float r = w - __bfloat162float(h);
    hi[idx] = h;
    lo[idx] = __float2bfloat16_rn(r);
}

// ---------------- scan ----------------
__global__ void scan1_kernel(int n)
{
    __shared__ int s[SCAN_B];
    int i = blockIdx.x * SCAN_B + threadIdx.x;
    s[threadIdx.x] = (i < n) ? g_degi[i] : 0;
    __syncthreads();
    for (int ofs = SCAN_B / 2; ofs > 0; ofs >>= 1) {
        if (threadIdx.x < ofs) s[threadIdx.x] += s[threadIdx.x + ofs];
        __syncthreads();
    }
    if (threadIdx.x == 0) g_part[blockIdx.x] = s[0];
}

__global__ void scan2_kernel(int nblocks, int n, int E)
{
    __shared__ int a[512], b[512];
    int t = threadIdx.x;
    int v = (t < nblocks) ? g_part[t] : 0;
    a[t] = v;
    __syncthreads();
    int* pin = a; int* pout = b;
    for (int ofs = 1; ofs < 512; ofs <<= 1) {
        pout[t] = (t >= ofs) ? pin[t] + pin[t - ofs] : pin[t];
        __syncthreads();
        int* tmp = pin; pin = pout; pout = tmp;
    }
    g_part[t] = (t == 0) ? 0 : pin[t - 1];
    if (t == 0) g_off[n] = E;
}

__global__ void scan3_kernel(int n)
{
    __shared__ int a[SCAN_B], b[SCAN_B];
    int t = threadIdx.x;
    int i = blockIdx.x * SCAN_B + t;
    int v = (i < n) ? g_degi[i] : 0;
    a[t] = v;
    __syncthreads();
    int* pin = a; int* pout = b;
    for (int ofs = 1; ofs < SCAN_B; ofs <<= 1) {
        pout[t] = (t >= ofs) ? pin[t] + pin[t - ofs] : pin[t];
        __syncthreads();
        int* tmp = pin; pin = pout; pout = tmp;
    }
    if (i < n) {
        int excl = (t == 0) ? 0 : pin[t - 1];
        int off = g_part[blockIdx.x] + excl;
        g_off[i] = off;
        g_cur[i] = off;
    }
}

// ---------------- scatter edges into CSR buckets with precomputed coef ----------------
__global__ void scatter_kernel(const int* __restrict__ src, const int* __restrict__ dst, int E)
{
    int e = blockIdx.x * blockDim.x + threadIdx.x;
    if (e < E) {
        int s = src[e];
        int d = dst[e];
        float coef = __ldg(&g_dinv[s]) * __ldg(&g_dinv[d]);
        int pos = atomicAdd(&g_cur[d], 1);
        g_epack[pos] = make_int2(s, __float_as_int(coef));
    }
}

// ---------------- HMMA GEMM v3: C_bf16[M,256] = A[M,K] @ W[K,256] ----------------
// CTA 128x256, 512 threads / 16 warps (warp tile 32x64), BK=64.
// 2-pass split: C = Ahi*Bhi + Ahi*Blo (A-rounding noise pools away downstream).
#define SA_HI 0
#define SB_HI 16384
#define SB_LO 49152
#define SM_TOTAL 81920

__global__ __launch_bounds__(512, 1)
void tgemm_kernel(const float* __restrict__ A,
                  const __nv_bfloat16* __restrict__ WHI,
                  const __nv_bfloat16* __restrict__ WLO,
                  __nv_bfloat16* __restrict__ C, int M, int K)
{
    extern __shared__ char smem[];
    const uint32_t sb = smem_u32(smem);
    const int tid = threadIdx.x;
    const int wid = tid >> 5;
    const int lane = tid & 31;
    const int warp_m = wid & 3;     // 0..3 -> 32 rows each
    const int warp_n = wid >> 2;    // 0..3 -> 64 cols each
    const int row0 = blockIdx.x * 128;

    float acc[2][8][4];
#pragma unroll
    for (int mt = 0; mt < 2; mt++)
#pragma unroll
        for (int nt = 0; nt < 8; nt++)
#pragma unroll
            for (int q = 0; q < 4; q++) acc[mt][nt][q] = 0.0f;

    const int lr   = lane & 7;
    const int lsel = lane >> 3;

    for (int k0 = 0; k0 < K; k0 += 64) {
        // ---- stage A [128 x 64 fp32] -> bf16 hi into SW128 smem (2048 float4 / 512 thr) ----
#pragma unroll
        for (int i = 0; i < 4; i++) {
            const int idx = tid + (i << 9);
            const int row = idx >> 4;
            const int f   = idx & 15;
            const int grow = row0 + row;
            float4 a4 = make_float4(0.f, 0.f, 0.f, 0.f);
            if (grow < M)
                a4 = *reinterpret_cast<const float4*>(A + (size_t)grow * K + k0 + f * 4);
            __nv_bfloat162 ph0 = __float22bfloat162_rn(make_float2(a4.x, a4.y));
            __nv_bfloat162 ph1 = __float22bfloat162_rn(make_float2(a4.z, a4.w));
            uint2 uh;
            uh.x = *reinterpret_cast<uint32_t*>(&ph0);
            uh.y = *reinterpret_cast<uint32_t*>(&ph1);
            const uint32_t sw = SWZ(row * 128 + f * 8);
            *reinterpret_cast<uint2*>(smem + SA_HI + sw) = uh;
        }
        // ---- stage B [256 n-rows x 64 k] hi + lo (2048 uint4 each / 512 thr) ----
#pragma unroll
        for (int i = 0; i < 4; i++) {
            const int idx = tid + (i << 9);
            const int nr = idx >> 3;
            const int u  = idx & 7;
            const uint32_t sw = SWZ(nr * 128 + u * 16);
            *reinterpret_cast<uint4*>(smem + SB_HI + sw) =
                *(reinterpret_cast<const uint4*>(WHI + (size_t)nr * K + k0) + u);
            *reinterpret_cast<uint4*>(smem + SB_LO + sw) =
                *(reinterpret_cast<const uint4*>(WLO + (size_t)nr * K + k0) + u);
        }
        __syncthreads();

        // ---- 4 x k16 steps ----
#pragma unroll
        for (int kk = 0; kk < 4; kk++) {
            const int kb = kk * 32 + (lsel & 2) * 8;
            uint32_t ah[8];
#pragma unroll
            for (int mt = 0; mt < 2; mt++) {
                const int arow = warp_m * 32 + mt * 16 + (lsel & 1) * 8 + lr;
                const uint32_t aoff = SWZ(arow * 128 + kb);
                ldsm_x4(sb + SA_HI + aoff, ah[mt*4+0], ah[mt*4+1], ah[mt*4+2], ah[mt*4+3]);
            }
            uint32_t bh[16], bl[16];
#pragma unroll
            for (int p = 0; p < 4; p++) {
                const int brow = warp_n * 64 + p * 16 + (lsel >> 1) * 8 + lr;
                const uint32_t boff = SWZ(brow * 128 + kk * 32 + (lsel & 1) * 16);
                ldsm_x4(sb + SB_HI + boff, bh[p*4+0], bh[p*4+1], bh[p*4+2], bh[p*4+3]);
                ldsm_x4(sb + SB_LO + boff, bl[p*4+0], bl[p*4+1], bl[p*4+2], bl[p*4+3]);
            }
#pragma unroll
            for (int mt = 0; mt < 2; mt++) {
#pragma unroll
                for (int nt = 0; nt < 8; nt++) {
                    mma_bf16(acc[mt][nt], &ah[mt*4], &bh[nt*2]);
                    mma_bf16(acc[mt][nt], &ah[mt*4], &bl[nt*2]);
                }
            }
        }
        __syncthreads();
    }

    // ---- epilogue: direct bf16 stores ----
    const int tr = lane >> 2;
    const int tc = (lane & 3) * 2;
#pragma unroll
    for (int mt = 0; mt < 2; mt++) {
#pragma unroll
        for (int nt = 0; nt < 8; nt++) {
            const int col = warp_n * 64 + nt * 8 + tc;
            const int r0 = row0 + warp_m * 32 + mt * 16 + tr;
            if (r0 < M) {
                __nv_bfloat162 v = __float22bfloat162_rn(make_float2(acc[mt][nt][0], acc[mt][nt][1]));
                *reinterpret_cast<__nv_bfloat162*>(C + (size_t)r0 * HDIM + col) = v;
            }
            if (r0 + 8 < M) {
                __nv_bfloat162 v = __float22bfloat162_rn(make_float2(acc[mt][nt][2], acc[mt][nt][3]));
                *reinterpret_cast<__nv_bfloat162*>(C + (size_t)(r0 + 8) * HDIM + col) = v;
            }
        }
    }
}

// ---------------- pull aggregation + finalize (1 warp/node, bf16 messages) ----------------
__global__ __launch_bounds__(256)
void pull_kernel(const float* __restrict__ b, int n)
{
    const int wid  = threadIdx.x >> 5;
    const int lane = threadIdx.x & 31;
    const int d    = blockIdx.x * 8 + wid;
    if (d >= n) return;

    const int beg = g_off[d];
    const int end = g_off[d + 1];

    const uint4* __restrict__ T = reinterpret_cast<const uint4*>(g_tb);
    const int2*  __restrict__ P = g_epack;

    float acc[8] = {0.f, 0.f, 0.f, 0.f, 0.f, 0.f, 0.f, 0.f};

    int e = beg;
#pragma unroll 1
    for (; e + 4 <= end; e += 4) {
        int2 p0 = __ldg(P + e + 0);
        int2 p1 = __ldg(P + e + 1);
        int2 p2 = __ldg(P + e + 2);
        int2 p3 = __ldg(P + e + 3);
        uint4 v0 = __ldg(T + (size_t)p0.x * 32 + lane);
        uint4 v1 = __ldg(T + (size_t)p1.x * 32 + lane);
        uint4 v2 = __ldg(T + (size_t)p2.x * 32 + lane);
        uint4 v3 = __ldg(T + (size_t)p3.x * 32 + lane);
        acc8(acc, v0, __int_as_float(p0.y));
        acc8(acc, v1, __int_as_float(p1.y));
        acc8(acc, v2, __int_as_float(p2.y));
        acc8(acc, v3, __int_as_float(p3.y));
    }
    for (; e < end; e++) {
        int2 p = __ldg(P + e);
        uint4 v = __ldg(T + (size_t)p.x * 32 + lane);
        acc8(acc, v, __int_as_float(p.y));
    }

    const float dd = g_dinv[d];
    acc8(acc, __ldg(T + (size_t)d * 32 + lane), dd * dd);

    const float4* bp = reinterpret_cast<const float4*>(b) + lane * 2;
    float4 b0 = __ldg(bp);
    float4 b1 = __ldg(bp + 1);
    float4 r0, r1;
    r0.x = fmaxf(acc[0] + b0.x, 0.0f);
    r0.y = fmaxf(acc[1] + b0.y, 0.0f);
    r0.z = fmaxf(acc[2] + b0.z, 0.0f);
    r0.w = fmaxf(acc[3] + b0.w, 0.0f);
    r1.x = fmaxf(acc[4] + b1.x, 0.0f);
    r1.y = fmaxf(acc[5] + b1.y, 0.0f);
    r1.z = fmaxf(acc[6] + b1.z, 0.0f);
    r1.w = fmaxf(acc[7] + b1.w, 0.0f);

    float4* yp = reinterpret_cast<float4*>(g_y) + (size_t)d * H4 + lane * 2;
    yp[0] = r0;
    yp[1] = r1;
}

// ---------------- column sums ----------------
__global__ void colsum_kernel(int n)
{
    const int j = threadIdx.x;
    float s = 0.0f;
    for (int r = blockIdx.x; r < n; r += gridDim.x)
        s += g_y[(size_t)r * HDIM + j];
    atomicAdd(&g_gv[j], s);
}

// ---------------- final linear ----------------
__global__ void final_kernel(const float* __restrict__ Wl, const float* __restrict__ bl,
                             float* __restrict__ out, float invN)
{
    __shared__ float s[2];
    if (threadIdx.x < 2) s[threadIdx.x] = 0.0f;
    __syncthreads();
    const int j = threadIdx.x;
    const float gj = g_gv[j] * invN;
    atomicAdd(&s[0], gj * Wl[j * 2 + 0]);
    atomicAdd(&s[1], gj * Wl[j * 2 + 1]);
    __syncthreads();
    if (threadIdx.x < 2) out[threadIdx.x] = s[threadIdx.x] + bl[threadIdx.x];
}

// ---------------- launcher ----------------
extern "C" void kernel_launch(void* const* d_in, const int* in_sizes, int n_in,
                              void* d_out, int out_size)
{
    const float* x  = (const float*)d_in[0];
    const int*   ei = (const int*)  d_in[1];
    const float* W1 = (const float*)d_in[3];
    const float* b1 = (const float*)d_in[4];
    const float* W2 = (const float*)d_in[5];
    const float* b2 = (const float*)d_in[6];
    const float* Wl = (const float*)d_in[7];
    const float* bl = (const float*)d_in[8];
    float* out = (float*)d_out;

    const int n = in_sizes[0] / 128;   // 50000
    const int E = in_sizes[1] / 2;     // 800000

    const int* src = ei;
    const int* dst = ei + E;

    __nv_bfloat16* tb_ptr; cudaGetSymbolAddress((void**)&tb_ptr, g_tb);
    float* y_ptr;  cudaGetSymbolAddress((void**)&y_ptr,  g_y);
    __nv_bfloat16 *w1h, *w1l, *w2h, *w2l;
    cudaGetSymbolAddress((void**)&w1h, g_w1t_hi);
    cudaGetSymbolAddress((void**)&w1l, g_w1t_lo);
    cudaGetSymbolAddress((void**)&w2h, g_w2t_hi);
    cudaGetSymbolAddress((void**)&w2l, g_w2t_lo);

    cudaFuncSetAttribute(tgemm_kernel, cudaFuncAttributeMaxDynamicSharedMemorySize, SM_TOTAL);

    const int nScanBlocks = (n + SCAN_B - 1) / SCAN_B;

    // ---- graph preprocessing + weight split ----
    prep_kernel<<<(n + 255) / 256, 256>>>(n);
    deg_kernel<<<(E + 255) / 256, 256>>>(dst, E);
    wtrans_kernel<<<(HDIM * 128 + 255) / 256, 256>>>(W1, w1h, w1l, 128, HDIM);
    wtrans_kernel<<<(HDIM * HDIM + 255) / 256, 256>>>(W2, w2h, w2l, HDIM, HDIM);
    rsqrt_kernel<<<(n + 255) / 256, 256>>>(n);
    scan1_kernel<<<nScanBlocks, SCAN_B>>>(n);
    scan2_kernel<<<1, 512>>>(nScanBlocks, n, E);
    scan3_kernel<<<nScanBlocks, SCAN_B>>>(n);
    scatter_kernel<<<(E + 255) / 256, 256>>>(src, dst, E);

    const int gemmBlocks = (n + 127) / 128;   // 391
    const int pullBlocks = (n + 7) / 8;       // 6250

    // ---- layer 1 ----
    tgemm_kernel<<<gemmBlocks, 512, SM_TOTAL>>>(x, w1h, w1l, tb_ptr, n, 128);
    pull_kernel<<<pullBlocks, 256>>>(b1, n);

    // ---- layer 2 ----
    tgemm_kernel<<<gemmBlocks, 512, SM_TOTAL>>>(y_ptr, w2h, w2l, tb_ptr, n, HDIM);
    pull_kernel<<<pullBlocks, 256>>>(b2, n);

    // ---- mean pool + final linear ----
    colsum_kernel<<<592, HDIM>>>(n);
    final_kernel<<<1, HDIM>>>(Wl, bl, out, 1.0f / (float)n);
}

// round 8
// speedup vs baseline: 3.6088x; 1.0847x over previous
#include <cuda_runtime.h>
#include <cuda_bf16.h>
#include <cstddef>
#include <cstdint>

#define NMAX   50000
#define EMAX   800000
#define HDIM   256
#define H4     (HDIM / 4)
#define SCAN_B 256

// ---------------- scratch (device globals) ----------------
__device__ __align__(16) __nv_bfloat16 g_tb[(size_t)NMAX * HDIM];  // GEMM output (bf16 messages)
__device__ __align__(16) __nv_bfloat16 g_yb[(size_t)NMAX * HDIM];  // layer activations (bf16)
__device__ __align__(16) __nv_bfloat16 g_xb[(size_t)NMAX * 128];   // input features (bf16)
__device__ float g_dinv[NMAX];
__device__ int   g_degi[NMAX];
__device__ int   g_off [NMAX + 1];
__device__ int   g_cur [NMAX];
__device__ __align__(8) int2 g_epack[EMAX];   // {src, coef-as-int}
__device__ int   g_part[512];
__device__ float g_gv  [HDIM];
// bf16 split weights, transposed to [n][k]
__device__ __align__(16) __nv_bfloat16 g_w1t_hi[HDIM * 128];
__device__ __align__(16) __nv_bfloat16 g_w1t_lo[HDIM * 128];
__device__ __align__(16) __nv_bfloat16 g_w2t_hi[HDIM * HDIM];
__device__ __align__(16) __nv_bfloat16 g_w2t_lo[HDIM * HDIM];

// ---------------- helpers ----------------
__device__ __forceinline__ uint32_t smem_u32(const void* p) {
    uint32_t a;
    asm("{ .reg .u64 t; cvta.to.shared.u64 t, %1; cvt.u32.u64 %0, t; }" : "=r"(a) : "l"(p));
    return a;
}
#define SWZ(off) ((off) ^ (((off) >> 3) & 0x70))

__device__ __forceinline__ void cp16(uint32_t dst, const void* src) {
    asm volatile("cp.async.cg.shared.global [%0], [%1], 16;" :: "r"(dst), "l"(src));
}
#define CP_COMMIT() asm volatile("cp.async.commit_group;" ::: "memory")

__device__ __forceinline__ void ldsm_x4(uint32_t addr, uint32_t& r0, uint32_t& r1,
                                        uint32_t& r2, uint32_t& r3) {
    asm volatile("ldmatrix.sync.aligned.m8n8.x4.shared.b16 {%0,%1,%2,%3}, [%4];"
                 : "=r"(r0), "=r"(r1), "=r"(r2), "=r"(r3) : "r"(addr));
}

__device__ __forceinline__ void mma_bf16(float* d, const uint32_t* a, const uint32_t* b) {
    asm volatile("mma.sync.aligned.m16n8k16.row.col.f32.bf16.bf16.f32 "
                 "{%0,%1,%2,%3}, {%4,%5,%6,%7}, {%8,%9}, {%0,%1,%2,%3};"
                 : "+f"(d[0]), "+f"(d[1]), "+f"(d[2]), "+f"(d[3])
                 : "r"(a[0]), "r"(a[1]), "r"(a[2]), "r"(a[3]), "r"(b[0]), "r"(b[1]));
}

// bf16x8 (uint4) -> 8x fma into acc
__device__ __forceinline__ void acc8(float* acc, uint4 v, float c) {
    float2 f0 = __bfloat1622float2(*reinterpret_cast<__nv_bfloat162*>(&v.x));
    float2 f1 = __bfloat1622float2(*reinterpret_cast<__nv_bfloat162*>(&v.y));
    float2 f2 = __bfloat1622float2(*reinterpret_cast<__nv_bfloat162*>(&v.z));
    float2 f3 = __bfloat1622float2(*reinterpret_cast<__nv_bfloat162*>(&v.w));
    acc[0] = fmaf(c, f0.x, acc[0]); acc[1] = fmaf(c, f0.y, acc[1]);
    acc[2] = fmaf(c, f1.x, acc[2]); acc[3] = fmaf(c, f1.y, acc[3]);
    acc[4] = fmaf(c, f2.x, acc[4]); acc[5] = fmaf(c, f2.y, acc[5]);
    acc[6] = fmaf(c, f3.x, acc[6]); acc[7] = fmaf(c, f3.y, acc[7]);
}

// ---------------- prep ----------------
__global__ void prep_kernel(int n)
{
    int i = blockIdx.x * blockDim.x + threadIdx.x;
    if (i < n)    g_degi[i] = 0;
    if (i < HDIM) g_gv[i]   = 0.0f;
}

__global__ void deg_kernel(const int* __restrict__ dst, int E)
{
    int e = blockIdx.x * blockDim.x + threadIdx.x;
    if (e < E) atomicAdd(&g_degi[dst[e]], 1);
}

// ---------------- x fp32 -> bf16 ----------------
__global__ void xconv_kernel(const float* __restrict__ x, int total4)
{
    int i = blockIdx.x * blockDim.x + threadIdx.x;
    if (i >= total4) return;
    float4 v = reinterpret_cast<const float4*>(x)[i];
    __nv_bfloat162 p0 = __float22bfloat162_rn(make_float2(v.x, v.y));
    __nv_bfloat162 p1 = __float22bfloat162_rn(make_float2(v.z, v.w));
    uint2 u;
    u.x = *reinterpret_cast<uint32_t*>(&p0);
    u.y = *reinterpret_cast<uint32_t*>(&p1);
    reinterpret_cast<uint2*>(g_xb)[i] = u;
}

// ---------------- weight transpose + bf16 split ----------------
__global__ void wtrans_kernel(const float* __restrict__ W,
                              __nv_bfloat16* __restrict__ hi, __nv_bfloat16* __restrict__ lo,
                              int K, int N)
{
    int idx = blockIdx.x * 256 + threadIdx.x;
    if (idx >= N * K) return;
    int nn = idx / K, kk = idx - nn * K;
    float w = W[(size_t)kk * N + nn];
    __nv_bfloat16 h = __float2bfloat16_rn(w);
    float r = w - __bfloat162float(h);
    hi[idx] = h;
    lo[idx] = __float2bfloat16_rn(r);
}

// ---------------- scan (scan1 also computes dinv) ----------------
__global__ void scan1_kernel(int n)
{
    __shared__ int s[SCAN_B];
    int i = blockIdx.x * SCAN_B + threadIdx.x;
    int deg = (i < n) ? g_degi[i] : 0;
    if (i < n) g_dinv[i] = rsqrtf((float)deg + 1.0f);
    s[threadIdx.x] = deg;
    __syncthreads();
    for (int ofs = SCAN_B / 2; ofs > 0; ofs >>= 1) {
        if (threadIdx.x < ofs) s[threadIdx.x] += s[threadIdx.x + ofs];
        __syncthreads();
    }
    if (threadIdx.x == 0) g_part[blockIdx.x] = s[0];
}

__global__ void scan2_kernel(int nblocks, int n, int E)
{
    __shared__ int a[512], b[512];
    int t = threadIdx.x;
    int v = (t < nblocks) ? g_part[t] : 0;
    a[t] = v;
    __syncthreads();
    int* pin = a; int* pout = b;
    for (int ofs = 1; ofs < 512; ofs <<= 1) {
        pout[t] = (t >= ofs) ? pin[t] + pin[t - ofs] : pin[t];
        __syncthreads();
        int* tmp = pin; pin = pout; pout = tmp;
    }
    g_part[t] = (t == 0) ? 0 : pin[t - 1];
    if (t == 0) g_off[n] = E;
}

__global__ void scan3_kernel(int n)
{
    __shared__ int a[SCAN_B], b[SCAN_B];
    int t = threadIdx.x;
    int i = blockIdx.x * SCAN_B + t;
    int v = (i < n) ? g_degi[i] : 0;
    a[t] = v;
    __syncthreads();
    int* pin = a; int* pout = b;
    for (int ofs = 1; ofs < SCAN_B; ofs <<= 1) {
        pout[t] = (t >= ofs) ? pin[t] + pin[t - ofs] : pin[t];
        __syncthreads();
        int* tmp = pin; pin = pout; pout = tmp;
    }
    if (i < n) {
        int excl = (t == 0) ? 0 : pin[t - 1];
        int off = g_part[blockIdx.x] + excl;
        g_off[i] = off;
        g_cur[i] = off;
    }
}

__global__ void scatter_kernel(const int* __restrict__ src, const int* __restrict__ dst, int E)
{
    int e = blockIdx.x * blockDim.x + threadIdx.x;
    if (e < E) {
        int s = src[e];
        int d = dst[e];
        float coef = __ldg(&g_dinv[s]) * __ldg(&g_dinv[d]);
        int pos = atomicAdd(&g_cur[d], 1);
        g_epack[pos] = make_int2(s, __float_as_int(coef));
    }
}

// ---------------- HMMA GEMM v4: C_bf16[M,256] = A_bf16[M,K] @ W[K,256] ----------------
// CTA 128x256, 512 threads / 16 warps (warp tile 32x64), BK=64.
// bf16 A + cp.async double-buffered stages. 2-pass split: C = A*Bhi + A*Blo.
#define ST_A   0
#define ST_BH  16384
#define ST_BL  49152
#define STAGE  81920
#define SM_TOTAL (2 * STAGE)

__global__ __launch_bounds__(512, 1)
void tgemm_kernel(const __nv_bfloat16* __restrict__ A,
                  const __nv_bfloat16* __restrict__ WHI,
                  const __nv_bfloat16* __restrict__ WLO,
                  __nv_bfloat16* __restrict__ C, int M, int K)
{
    extern __shared__ char smem[];
    const uint32_t sb = smem_u32(smem);
    const int tid = threadIdx.x;
    const int wid = tid >> 5;
    const int lane = tid & 31;
    const int warp_m = wid & 3;
    const int warp_n = wid >> 2;
    const int row0 = blockIdx.x * 128;

    float acc[2][8][4];
#pragma unroll
    for (int mt = 0; mt < 2; mt++)
#pragma unroll
        for (int nt = 0; nt < 8; nt++)
#pragma unroll
            for (int q = 0; q < 4; q++) acc[mt][nt][q] = 0.0f;

    const int lr   = lane & 7;
    const int lsel = lane >> 3;
    const int nch  = K >> 6;

    // stage loader: A tile 1024 uint4 (2/thread), B hi/lo 2048 uint4 each (4/thread)
    auto stage_load = [&](int c, int buf) {
        const int k0 = c << 6;
        const uint32_t base = sb + buf * STAGE;
#pragma unroll
        for (int i = 0; i < 2; i++) {
            const int idx = tid + (i << 9);
            const int row = idx >> 3;
            const int u   = idx & 7;
            const int grow = min(row0 + row, M - 1);
            cp16(base + ST_A + SWZ(row * 128 + u * 16),
                 A + (size_t)grow * K + k0 + u * 8);
        }
#pragma unroll
        for (int i = 0; i < 4; i++) {
            const int idx = tid + (i << 9);
            const int nr = idx >> 3;
            const int u  = idx & 7;
            const uint32_t sw = SWZ(nr * 128 + u * 16);
            cp16(base + ST_BH + sw, WHI + (size_t)nr * K + k0 + u * 8);
            cp16(base + ST_BL + sw, WLO + (size_t)nr * K + k0 + u * 8);
        }
        CP_COMMIT();
    };

    stage_load(0, 0);

    for (int c = 0; c < nch; c++) {
        if (c + 1 < nch) {
            stage_load(c + 1, (c + 1) & 1);
            asm volatile("cp.async.wait_group 1;" ::: "memory");
        } else {
            asm volatile("cp.async.wait_group 0;" ::: "memory");
        }
        __syncthreads();

        const uint32_t bufb = sb + (c & 1) * STAGE;
#pragma unroll
        for (int kk = 0; kk < 4; kk++) {
            const int kb = kk * 32 + (lsel & 2) * 8;
            uint32_t ah[8];
#pragma unroll
            for (int mt = 0; mt < 2; mt++) {
                const int arow = warp_m * 32 + mt * 16 + (lsel & 1) * 8 + lr;
                const uint32_t aoff = SWZ(arow * 128 + kb);
                ldsm_x4(bufb + ST_A + aoff, ah[mt*4+0], ah[mt*4+1], ah[mt*4+2], ah[mt*4+3]);
            }
            uint32_t bh[16], bl[16];
#pragma unroll
            for (int p = 0; p < 4; p++) {
                const int brow = warp_n * 64 + p * 16 + (lsel >> 1) * 8 + lr;
                const uint32_t boff = SWZ(brow * 128 + kk * 32 + (lsel & 1) * 16);
                ldsm_x4(bufb + ST_BH + boff, bh[p*4+0], bh[p*4+1], bh[p*4+2], bh[p*4+3]);
                ldsm_x4(bufb + ST_BL + boff, bl[p*4+0], bl[p*4+1], bl[p*4+2], bl[p*4+3]);
            }
#pragma unroll
            for (int mt = 0; mt < 2; mt++) {
#pragma unroll
                for (int nt = 0; nt < 8; nt++) {
                    mma_bf16(acc[mt][nt], &ah[mt*4], &bh[nt*2]);
                    mma_bf16(acc[mt][nt], &ah[mt*4], &bl[nt*2]);
                }
            }
        }
        __syncthreads();
    }

    // ---- epilogue: direct bf16 stores ----
    const int tr = lane >> 2;
    const int tc = (lane & 3) * 2;
#pragma unroll
    for (int mt = 0; mt < 2; mt++) {
#pragma unroll
        for (int nt = 0; nt < 8; nt++) {
            const int col = warp_n * 64 + nt * 8 + tc;
            const int r0 = row0 + warp_m * 32 + mt * 16 + tr;
            if (r0 < M) {
                __nv_bfloat162 v = __float22bfloat162_rn(make_float2(acc[mt][nt][0], acc[mt][nt][1]));
                *reinterpret_cast<__nv_bfloat162*>(C + (size_t)r0 * HDIM + col) = v;
            }
            if (r0 + 8 < M) {
                __nv_bfloat162 v = __float22bfloat162_rn(make_float2(acc[mt][nt][2], acc[mt][nt][3]));
                *reinterpret_cast<__nv_bfloat162*>(C + (size_t)(r0 + 8) * HDIM + col) = v;
            }
        }
    }
}

// ---------------- pull aggregation + finalize (1 warp/node, bf16 in/out) ----------------
__global__ __launch_bounds__(256)
void pull_kernel(const float* __restrict__ b, int n)
{
    const int wid  = threadIdx.x >> 5;
    const int lane = threadIdx.x & 31;
    const int d    = blockIdx.x * 8 + wid;
    if (d >= n) return;

    const int beg = g_off[d];
    const int end = g_off[d + 1];

    const uint4* __restrict__ T = reinterpret_cast<const uint4*>(g_tb);
    const int2*  __restrict__ P = g_epack;

    float acc[8] = {0.f, 0.f, 0.f, 0.f, 0.f, 0.f, 0.f, 0.f};

    int e = beg;
#pragma unroll 1
    for (; e + 4 <= end; e += 4) {
        int2 p0 = __ldg(P + e + 0);
        int2 p1 = __ldg(P + e + 1);
        int2 p2 = __ldg(P + e + 2);
        int2 p3 = __ldg(P + e + 3);
        uint4 v0 = __ldg(T + (size_t)p0.x * 32 + lane);
        uint4 v1 = __ldg(T + (size_t)p1.x * 32 + lane);
        uint4 v2 = __ldg(T + (size_t)p2.x * 32 + lane);
        uint4 v3 = __ldg(T + (size_t)p3.x * 32 + lane);
        acc8(acc, v0, __int_as_float(p0.y));
        acc8(acc, v1, __int_as_float(p1.y));
        acc8(acc, v2, __int_as_float(p2.y));
        acc8(acc, v3, __int_as_float(p3.y));
    }
    for (; e < end; e++) {
        int2 p = __ldg(P + e);
        uint4 v = __ldg(T + (size_t)p.x * 32 + lane);
        acc8(acc, v, __int_as_float(p.y));
    }

    const float dd = g_dinv[d];
    acc8(acc, __ldg(T + (size_t)d * 32 + lane), dd * dd);

    const float4* bp = reinterpret_cast<const float4*>(b) + lane * 2;
    float4 b0 = __ldg(bp);
    float4 b1 = __ldg(bp + 1);

    float r0 = fmaxf(acc[0] + b0.x, 0.0f);
    float r1 = fmaxf(acc[1] + b0.y, 0.0f);
    float r2 = fmaxf(acc[2] + b0.z, 0.0f);
    float r3 = fmaxf(acc[3] + b0.w, 0.0f);
    float r4 = fmaxf(acc[4] + b1.x, 0.0f);
    float r5 = fmaxf(acc[5] + b1.y, 0.0f);
    float r6 = fmaxf(acc[6] + b1.z, 0.0f);
    float r7 = fmaxf(acc[7] + b1.w, 0.0f);

    __nv_bfloat162 o0 = __float22bfloat162_rn(make_float2(r0, r1));
    __nv_bfloat162 o1 = __float22bfloat162_rn(make_float2(r2, r3));
    __nv_bfloat162 o2 = __float22bfloat162_rn(make_float2(r4, r5));
    __nv_bfloat162 o3 = __float22bfloat162_rn(make_float2(r6, r7));
    uint4 o;
    o.x = *reinterpret_cast<uint32_t*>(&o0);
    o.y = *reinterpret_cast<uint32_t*>(&o1);
    o.z = *reinterpret_cast<uint32_t*>(&o2);
    o.w = *reinterpret_cast<uint32_t*>(&o3);
    reinterpret_cast<uint4*>(g_yb)[(size_t)d * 32 + lane] = o;
}

// ---------------- column sums (bf16 input) ----------------
__global__ void colsum_kernel(int n)
{
    const int j = threadIdx.x;
    float s = 0.0f;
    for (int r = blockIdx.x; r < n; r += gridDim.x)
        s += __bfloat162float(g_yb[(size_t)r * HDIM + j]);
    atomicAdd(&g_gv[j], s);
}

// ---------------- final linear ----------------
__global__ void final_kernel(const float* __restrict__ Wl, const float* __restrict__ bl,
                             float* __restrict__ out, float invN)
{
    __shared__ float s[2];
    if (threadIdx.x < 2) s[threadIdx.x] = 0.0f;
    __syncthreads();
    const int j = threadIdx.x;
    const float gj = g_gv[j] * invN;
    atomicAdd(&s[0], gj * Wl[j * 2 + 0]);
    atomicAdd(&s[1], gj * Wl[j * 2 + 1]);
    __syncthreads();
    if (threadIdx.x < 2) out[threadIdx.x] = s[threadIdx.x] + bl[threadIdx.x];
}

// ---------------- launcher ----------------
extern "C" void kernel_launch(void* const* d_in, const int* in_sizes, int n_in,
                              void* d_out, int out_size)
{
    const float* x  = (const float*)d_in[0];
    const int*   ei = (const int*)  d_in[1];
    const float* W1 = (const float*)d_in[3];
    const float* b1 = (const float*)d_in[4];
    const float* W2 = (const float*)d_in[5];
    const float* b2 = (const float*)d_in[6];
    const float* Wl = (const float*)d_in[7];
    const float* bl = (const float*)d_in[8];
    float* out = (float*)d_out;

    const int n = in_sizes[0] / 128;   // 50000
    const int E = in_sizes[1] / 2;     // 800000

    const int* src = ei;
    const int* dst = ei + E;

    __nv_bfloat16 *tb_ptr, *yb_ptr, *xb_ptr;
    cudaGetSymbolAddress((void**)&tb_ptr, g_tb);
    cudaGetSymbolAddress((void**)&yb_ptr, g_yb);
    cudaGetSymbolAddress((void**)&xb_ptr, g_xb);
    __nv_bfloat16 *w1h, *w1l, *w2h, *w2l;
    cudaGetSymbolAddress((void**)&w1h, g_w1t_hi);
    cudaGetSymbolAddress((void**)&w1l, g_w1t_lo);
    cudaGetSymbolAddress((void**)&w2h, g_w2t_hi);
    cudaGetSymbolAddress((void**)&w2l, g_w2t_lo);

    cudaFuncSetAttribute(tgemm_kernel, cudaFuncAttributeMaxDynamicSharedMemorySize, SM_TOTAL);

    const int nScanBlocks = (n + SCAN_B - 1) / SCAN_B;

    // ---- graph preprocessing + conversions ----
    prep_kernel<<<(n + 255) / 256, 256>>>(n);
    deg_kernel<<<(E + 255) / 256, 256>>>(dst, E);
    xconv_kernel<<<(n * 32 + 255) / 256, 256>>>(x, n * 32);
    wtrans_kernel<<<(HDIM * 128 + 255) / 256, 256>>>(W1, w1h, w1l, 128, HDIM);
    wtrans_kernel<<<(HDIM * HDIM + 255) / 256, 256>>>(W2, w2h, w2l, HDIM, HDIM);
    scan1_kernel<<<nScanBlocks, SCAN_B>>>(n);
    scan2_kernel<<<1, 512>>>(nScanBlocks, n, E);
    scan3_kernel<<<nScanBlocks, SCAN_B>>>(n);
    scatter_kernel<<<(E + 255) / 256, 256>>>(src, dst, E);

    const int gemmBlocks = (n + 127) / 128;   // 391
    const int pullBlocks = (n + 7) / 8;       // 6250

    // ---- layer 1 ----
    tgemm_kernel<<<gemmBlocks, 512, SM_TOTAL>>>(xb_ptr, w1h, w1l, tb_ptr, n, 128);
    pull_kernel<<<pullBlocks, 256>>>(b1, n);

    // ---- layer 2 ----
    tgemm_kernel<<<gemmBlocks, 512, SM_TOTAL>>>(yb_ptr, w2h, w2l, tb_ptr, n, HDIM);
    pull_kernel<<<pullBlocks, 256>>>(b2, n);

    // ---- mean pool + final linear ----
    colsum_kernel<<<592, HDIM>>>(n);
    final_kernel<<<1, HDIM>>>(Wl, bl, out, 1.0f / (float)n);
}

// round 9
// speedup vs baseline: 3.9089x; 1.0832x over previous
#include <cuda_runtime.h>
#include <cuda_bf16.h>
#include <cstddef>
#include <cstdint>

#define NMAX   50000
#define EMAX   800000
#define HDIM   256
#define H4     (HDIM / 4)
#define SCAN_B 256

// ---------------- scratch (device globals) ----------------
__device__ __align__(16) __nv_bfloat16 g_tb[(size_t)NMAX * HDIM];  // GEMM output (bf16 messages)
__device__ __align__(16) __nv_bfloat16 g_yb[(size_t)NMAX * HDIM];  // layer activations (bf16)
__device__ __align__(16) __nv_bfloat16 g_xb[(size_t)NMAX * 128];   // input features (bf16)
__device__ float g_dinv[NMAX];
__device__ int   g_degi[NMAX];
__device__ int   g_off [NMAX + 1];
__device__ int   g_cur [NMAX];
__device__ __align__(8) int2 g_epack[EMAX];   // {src, coef-as-int}
__device__ int   g_part[512];
__device__ float g_gv  [HDIM];
// bf16 split weights, transposed to [n][k]
__device__ __align__(16) __nv_bfloat16 g_w1t_hi[HDIM * 128];
__device__ __align__(16) __nv_bfloat16 g_w1t_lo[HDIM * 128];
__device__ __align__(16) __nv_bfloat16 g_w2t_hi[HDIM * HDIM];
__device__ __align__(16) __nv_bfloat16 g_w2t_lo[HDIM * HDIM];

// ---------------- side stream + events (created once at load; not device allocs) ---
struct SideStream {
    cudaStream_t s;
    cudaEvent_t  fork, join;
    SideStream() {
        cudaStreamCreateWithFlags(&s, cudaStreamNonBlocking);
        cudaEventCreateWithFlags(&fork, cudaEventDisableTiming);
        cudaEventCreateWithFlags(&join, cudaEventDisableTiming);
    }
};
static SideStream g_side;

// ---------------- helpers ----------------
__device__ __forceinline__ uint32_t smem_u32(const void* p) {
    uint32_t a;
    asm("{ .reg .u64 t; cvta.to.shared.u64 t, %1; cvt.u32.u64 %0, t; }" : "=r"(a) : "l"(p));
    return a;
}
#define SWZ(off) ((off) ^ (((off) >> 3) & 0x70))

__device__ __forceinline__ void cp16(uint32_t dst, const void* src) {
    asm volatile("cp.async.cg.shared.global [%0], [%1], 16;" :: "r"(dst), "l"(src));
}
#define CP_COMMIT() asm volatile("cp.async.commit_group;" ::: "memory")

__device__ __forceinline__ void ldsm_x4(uint32_t addr, uint32_t& r0, uint32_t& r1,
                                        uint32_t& r2, uint32_t& r3) {
    asm volatile("ldmatrix.sync.aligned.m8n8.x4.shared.b16 {%0,%1,%2,%3}, [%4];"
                 : "=r"(r0), "=r"(r1), "=r"(r2), "=r"(r3) : "r"(addr));
}

__device__ __forceinline__ void mma_bf16(float* d, const uint32_t* a, const uint32_t* b) {
    asm volatile("mma.sync.aligned.m16n8k16.row.col.f32.bf16.bf16.f32 "
                 "{%0,%1,%2,%3}, {%4,%5,%6,%7}, {%8,%9}, {%0,%1,%2,%3};"
                 : "+f"(d[0]), "+f"(d[1]), "+f"(d[2]), "+f"(d[3])
                 : "r"(a[0]), "r"(a[1]), "r"(a[2]), "r"(a[3]), "r"(b[0]), "r"(b[1]));
}

// bf16x8 (uint4) -> 8x fma into acc
__device__ __forceinline__ void acc8(float* acc, uint4 v, float c) {
    float2 f0 = __bfloat1622float2(*reinterpret_cast<__nv_bfloat162*>(&v.x));
    float2 f1 = __bfloat1622float2(*reinterpret_cast<__nv_bfloat162*>(&v.y));
    float2 f2 = __bfloat1622float2(*reinterpret_cast<__nv_bfloat162*>(&v.z));
    float2 f3 = __bfloat1622float2(*reinterpret_cast<__nv_bfloat162*>(&v.w));
    acc[0] = fmaf(c, f0.x, acc[0]); acc[1] = fmaf(c, f0.y, acc[1]);
    acc[2] = fmaf(c, f1.x, acc[2]); acc[3] = fmaf(c, f1.y, acc[3]);
    acc[4] = fmaf(c, f2.x, acc[4]); acc[5] = fmaf(c, f2.y, acc[5]);
    acc[6] = fmaf(c, f3.x, acc[6]); acc[7] = fmaf(c, f3.y, acc[7]);
}

// ---------------- fused conversions: xconv + wtrans(W1) + wtrans(W2) + zero gv ----
__global__ void convall_kernel(const float* __restrict__ x,
                               const float* __restrict__ W1,
                               const float* __restrict__ W2, int n)
{
    const int idx = blockIdx.x * 256 + threadIdx.x;
    // W1 split-transpose: [128,256] -> hi/lo [256][128]
    if (idx < HDIM * 128) {
        int nn = idx >> 7, kk = idx & 127;
        float w = W1[(size_t)kk * HDIM + nn];
        __nv_bfloat16 h = __float2bfloat16_rn(w);
        g_w1t_hi[idx] = h;
        g_w1t_lo[idx] = __float2bfloat16_rn(w - __bfloat162float(h));
    }
    // W2 split-transpose: [256,256] -> hi/lo [256][256]
    if (idx < HDIM * HDIM) {
        int nn = idx >> 8, kk = idx & 255;
        float w = W2[(size_t)kk * HDIM + nn];
        __nv_bfloat16 h = __float2bfloat16_rn(w);
        g_w2t_hi[idx] = h;
        g_w2t_lo[idx] = __float2bfloat16_rn(w - __bfloat162float(h));
    }
    if (idx < HDIM) g_gv[idx] = 0.0f;
    // x fp32 -> bf16 (float4 granularity)
    if (idx < n * 32) {
        float4 v = reinterpret_cast<const float4*>(x)[idx];
        __nv_bfloat162 p0 = __float22bfloat162_rn(make_float2(v.x, v.y));
        __nv_bfloat162 p1 = __float22bfloat162_rn(make_float2(v.z, v.w));
        uint2 u;
        u.x = *reinterpret_cast<uint32_t*>(&p0);
        u.y = *reinterpret_cast<uint32_t*>(&p1);
        reinterpret_cast<uint2*>(g_xb)[idx] = u;
    }
}

// ---------------- CSR-build chain (side stream) ----------------
__global__ void prep_kernel(int n)
{
    int i = blockIdx.x * blockDim.x + threadIdx.x;
    if (i < n) g_degi[i] = 0;
}

__global__ void deg_kernel(const int* __restrict__ dst, int E)
{
    int e = blockIdx.x * blockDim.x + threadIdx.x;
    if (e < E) atomicAdd(&g_degi[dst[e]], 1);
}

__global__ void scan1_kernel(int n)
{
    __shared__ int s[SCAN_B];
    int i = blockIdx.x * SCAN_B + threadIdx.x;
    int deg = (i < n) ? g_degi[i] : 0;
    if (i < n) g_dinv[i] = rsqrtf((float)deg + 1.0f);
    s[threadIdx.x] = deg;
    __syncthreads();
    for (int ofs = SCAN_B / 2; ofs > 0; ofs >>= 1) {
        if (threadIdx.x < ofs) s[threadIdx.x] += s[threadIdx.x + ofs];
        __syncthreads();
    }
    if (threadIdx.x == 0) g_part[blockIdx.x] = s[0];
}

__global__ void scan2_kernel(int nblocks, int n, int E)
{
    __shared__ int a[512], b[512];
    int t = threadIdx.x;
    int v = (t < nblocks) ? g_part[t] : 0;
    a[t] = v;
    __syncthreads();
    int* pin = a; int* pout = b;
    for (int ofs = 1; ofs < 512; ofs <<= 1) {
        pout[t] = (t >= ofs) ? pin[t] + pin[t - ofs] : pin[t];
        __syncthreads();
        int* tmp = pin; pin = pout; pout = tmp;
    }
    g_part[t] = (t == 0) ? 0 : pin[t - 1];
    if (t == 0) g_off[n] = E;
}

__global__ void scan3_kernel(int n)
{
    __shared__ int a[SCAN_B], b[SCAN_B];
    int t = threadIdx.x;
    int i = blockIdx.x * SCAN_B + t;
    int v = (i < n) ? g_degi[i] : 0;
    a[t] = v;
    __syncthreads();
    int* pin = a; int* pout = b;
    for (int ofs = 1; ofs < SCAN_B; ofs <<= 1) {
        pout[t] = (t >= ofs) ? pin[t] + pin[t - ofs] : pin[t];
        __syncthreads();
        int* tmp = pin; pin = pout; pout = tmp;
    }
    if (i < n) {
        int excl = (t == 0) ? 0 : pin[t - 1];
        int off = g_part[blockIdx.x] + excl;
        g_off[i] = off;
        g_cur[i] = off;
    }
}

__global__ void scatter_kernel(const int* __restrict__ src, const int* __restrict__ dst, int E)
{
    int e = blockIdx.x * blockDim.x + threadIdx.x;
    if (e < E) {
        int s = src[e];
        int d = dst[e];
        float coef = __ldg(&g_dinv[s]) * __ldg(&g_dinv[d]);
        int pos = atomicAdd(&g_cur[d], 1);
        g_epack[pos] = make_int2(s, __float_as_int(coef));
    }
}

// ---------------- HMMA GEMM v4: C_bf16[M,256] = A_bf16[M,K] @ W[K,256] ----------------
#define ST_A   0
#define ST_BH  16384
#define ST_BL  49152
#define STAGE  81920
#define SM_TOTAL (2 * STAGE)

__global__ __launch_bounds__(512, 1)
void tgemm_kernel(const __nv_bfloat16* __restrict__ A,
                  const __nv_bfloat16* __restrict__ WHI,
                  const __nv_bfloat16* __restrict__ WLO,
                  __nv_bfloat16* __restrict__ C, int M, int K)
{
    extern __shared__ char smem[];
    const uint32_t sb = smem_u32(smem);
    const int tid = threadIdx.x;
    const int wid = tid >> 5;
    const int lane = tid & 31;
    const int warp_m = wid & 3;
    const int warp_n = wid >> 2;
    const int row0 = blockIdx.x * 128;

    float acc[2][8][4];
#pragma unroll
    for (int mt = 0; mt < 2; mt++)
#pragma unroll
        for (int nt = 0; nt < 8; nt++)
#pragma unroll
            for (int q = 0; q < 4; q++) acc[mt][nt][q] = 0.0f;

    const int lr   = lane & 7;
    const int lsel = lane >> 3;
    const int nch  = K >> 6;

    auto stage_load = [&](int c, int buf) {
        const int k0 = c << 6;
        const uint32_t base = sb + buf * STAGE;
#pragma unroll
        for (int i = 0; i < 2; i++) {
            const int idx = tid + (i << 9);
            const int row = idx >> 3;
            const int u   = idx & 7;
            const int grow = min(row0 + row, M - 1);
            cp16(base + ST_A + SWZ(row * 128 + u * 16),
                 A + (size_t)grow * K + k0 + u * 8);
        }
#pragma unroll
        for (int i = 0; i < 4; i++) {
            const int idx = tid + (i << 9);
            const int nr = idx >> 3;
            const int u  = idx & 7;
            const uint32_t sw = SWZ(nr * 128 + u * 16);
            cp16(base + ST_BH + sw, WHI + (size_t)nr * K + k0 + u * 8);
            cp16(base + ST_BL + sw, WLO + (size_t)nr * K + k0 + u * 8);
        }
        CP_COMMIT();
    };

    stage_load(0, 0);

    for (int c = 0; c < nch; c++) {
        if (c + 1 < nch) {
            stage_load(c + 1, (c + 1) & 1);
            asm volatile("cp.async.wait_group 1;" ::: "memory");
        } else {
            asm volatile("cp.async.wait_group 0;" ::: "memory");
        }
        __syncthreads();

        const uint32_t bufb = sb + (c & 1) * STAGE;
#pragma unroll
        for (int kk = 0; kk < 4; kk++) {
            const int kb = kk * 32 + (lsel & 2) * 8;
            uint32_t ah[8];
#pragma unroll
            for (int mt = 0; mt < 2; mt++) {
                const int arow = warp_m * 32 + mt * 16 + (lsel & 1) * 8 + lr;
                const uint32_t aoff = SWZ(arow * 128 + kb);
                ldsm_x4(bufb + ST_A + aoff, ah[mt*4+0], ah[mt*4+1], ah[mt*4+2], ah[mt*4+3]);
            }
            uint32_t bh[16], bl[16];
#pragma unroll
            for (int p = 0; p < 4; p++) {
                const int brow = warp_n * 64 + p * 16 + (lsel >> 1) * 8 + lr;
                const uint32_t boff = SWZ(brow * 128 + kk * 32 + (lsel & 1) * 16);
                ldsm_x4(bufb + ST_BH + boff, bh[p*4+0], bh[p*4+1], bh[p*4+2], bh[p*4+3]);
                ldsm_x4(bufb + ST_BL + boff, bl[p*4+0], bl[p*4+1], bl[p*4+2], bl[p*4+3]);
            }
#pragma unroll
            for (int mt = 0; mt < 2; mt++) {
#pragma unroll
                for (int nt = 0; nt < 8; nt++) {
                    mma_bf16(acc[mt][nt], &ah[mt*4], &bh[nt*2]);
                    mma_bf16(acc[mt][nt], &ah[mt*4], &bl[nt*2]);
                }
            }
        }
        __syncthreads();
    }

    const int tr = lane >> 2;
    const int tc = (lane & 3) * 2;
#pragma unroll
    for (int mt = 0; mt < 2; mt++) {
#pragma unroll
        for (int nt = 0; nt < 8; nt++) {
            const int col = warp_n * 64 + nt * 8 + tc;
            const int r0 = row0 + warp_m * 32 + mt * 16 + tr;
            if (r0 < M) {
                __nv_bfloat162 v = __float22bfloat162_rn(make_float2(acc[mt][nt][0], acc[mt][nt][1]));
                *reinterpret_cast<__nv_bfloat162*>(C + (size_t)r0 * HDIM + col) = v;
            }
            if (r0 + 8 < M) {
                __nv_bfloat162 v = __float22bfloat162_rn(make_float2(acc[mt][nt][2], acc[mt][nt][3]));
                *reinterpret_cast<__nv_bfloat162*>(C + (size_t)(r0 + 8) * HDIM + col) = v;
            }
        }
    }
}

// ---------------- pull aggregation + finalize (1 warp/node, bf16 in/out) ----------------
__global__ __launch_bounds__(256)
void pull_kernel(const float* __restrict__ b, int n)
{
    const int wid  = threadIdx.x >> 5;
    const int lane = threadIdx.x & 31;
    const int d    = blockIdx.x * 8 + wid;
    if (d >= n) return;

    const int beg = g_off[d];
    const int end = g_off[d + 1];

    const uint4* __restrict__ T = reinterpret_cast<const uint4*>(g_tb);
    const int2*  __restrict__ P = g_epack;

    float acc[8] = {0.f, 0.f, 0.f, 0.f, 0.f, 0.f, 0.f, 0.f};

    int e = beg;
#pragma unroll 1
    for (; e + 4 <= end; e += 4) {
        int2 p0 = __ldg(P + e + 0);
        int2 p1 = __ldg(P + e + 1);
        int2 p2 = __ldg(P + e + 2);
        int2 p3 = __ldg(P + e + 3);
        uint4 v0 = __ldg(T + (size_t)p0.x * 32 + lane);
        uint4 v1 = __ldg(T + (size_t)p1.x * 32 + lane);
        uint4 v2 = __ldg(T + (size_t)p2.x * 32 + lane);
        uint4 v3 = __ldg(T + (size_t)p3.x * 32 + lane);
        acc8(acc, v0, __int_as_float(p0.y));
        acc8(acc, v1, __int_as_float(p1.y));
        acc8(acc, v2, __int_as_float(p2.y));
        acc8(acc, v3, __int_as_float(p3.y));
    }
    for (; e < end; e++) {
        int2 p = __ldg(P + e);
        uint4 v = __ldg(T + (size_t)p.x * 32 + lane);
        acc8(acc, v, __int_as_float(p.y));
    }

    const float dd = g_dinv[d];
    acc8(acc, __ldg(T + (size_t)d * 32 + lane), dd * dd);

    const float4* bp = reinterpret_cast<const float4*>(b) + lane * 2;
    float4 b0 = __ldg(bp);
    float4 b1 = __ldg(bp + 1);

    float r0 = fmaxf(acc[0] + b0.x, 0.0f);
    float r1 = fmaxf(acc[1] + b0.y, 0.0f);
    float r2 = fmaxf(acc[2] + b0.z, 0.0f);
    float r3 = fmaxf(acc[3] + b0.w, 0.0f);
    float r4 = fmaxf(acc[4] + b1.x, 0.0f);
    float r5 = fmaxf(acc[5] + b1.y, 0.0f);
    float r6 = fmaxf(acc[6] + b1.z, 0.0f);
    float r7 = fmaxf(acc[7] + b1.w, 0.0f);

    __nv_bfloat162 o0 = __float22bfloat162_rn(make_float2(r0, r1));
    __nv_bfloat162 o1 = __float22bfloat162_rn(make_float2(r2, r3));
    __nv_bfloat162 o2 = __float22bfloat162_rn(make_float2(r4, r5));
    __nv_bfloat162 o3 = __float22bfloat162_rn(make_float2(r6, r7));
    uint4 o;
    o.x = *reinterpret_cast<uint32_t*>(&o0);
    o.y = *reinterpret_cast<uint32_t*>(&o1);
    o.z = *reinterpret_cast<uint32_t*>(&o2);
    o.w = *reinterpret_cast<uint32_t*>(&o3);
    reinterpret_cast<uint4*>(g_yb)[(size_t)d * 32 + lane] = o;
}

// ---------------- column sums (bf16 input) ----------------
__global__ void colsum_kernel(int n)
{
    const int j = threadIdx.x;
    float s = 0.0f;
    for (int r = blockIdx.x; r < n; r += gridDim.x)
        s += __bfloat162float(g_yb[(size_t)r * HDIM + j]);
    atomicAdd(&g_gv[j], s);
}

// ---------------- final linear ----------------
__global__ void final_kernel(const float* __restrict__ Wl, const float* __restrict__ bl,
                             float* __restrict__ out, float invN)
{
    __shared__ float s[2];
    if (threadIdx.x < 2) s[threadIdx.x] = 0.0f;
    __syncthreads();
    const int j = threadIdx.x;
    const float gj = g_gv[j] * invN;
    atomicAdd(&s[0], gj * Wl[j * 2 + 0]);
    atomicAdd(&s[1], gj * Wl[j * 2 + 1]);
    __syncthreads();
    if (threadIdx.x < 2) out[threadIdx.x] = s[threadIdx.x] + bl[threadIdx.x];
}

// ---------------- launcher ----------------
extern "C" void kernel_launch(void* const* d_in, const int* in_sizes, int n_in,
                              void* d_out, int out_size)
{
    const float* x  = (const float*)d_in[0];
    const int*   ei = (const int*)  d_in[1];
    const float* W1 = (const float*)d_in[3];
    const float* b1 = (const float*)d_in[4];
    const float* W2 = (const float*)d_in[5];
    const float* b2 = (const float*)d_in[6];
    const float* Wl = (const float*)d_in[7];
    const float* bl = (const float*)d_in[8];
    float* out = (float*)d_out;

    const int n = in_sizes[0] / 128;   // 50000
    const int E = in_sizes[1] / 2;     // 800000

    const int* src = ei;
    const int* dst = ei + E;

    __nv_bfloat16 *tb_ptr, *yb_ptr, *xb_ptr;
    cudaGetSymbolAddress((void**)&tb_ptr, g_tb);
    cudaGetSymbolAddress((void**)&yb_ptr, g_yb);
    cudaGetSymbolAddress((void**)&xb_ptr, g_xb);
    __nv_bfloat16 *w1h, *w1l, *w2h, *w2l;
    cudaGetSymbolAddress((void**)&w1h, g_w1t_hi);
    cudaGetSymbolAddress((void**)&w1l, g_w1t_lo);
    cudaGetSymbolAddress((void**)&w2h, g_w2t_hi);
    cudaGetSymbolAddress((void**)&w2l, g_w2t_lo);

    cudaFuncSetAttribute(tgemm_kernel, cudaFuncAttributeMaxDynamicSharedMemorySize, SM_TOTAL);

    const int nScanBlocks = (n + SCAN_B - 1) / SCAN_B;
    const int gemmBlocks = (n + 127) / 128;   // 391
    const int pullBlocks = (n + 7) / 8;       // 6250

    // ---- fork: CSR build on side stream, conversions + GEMM1 on main ----
    cudaEventRecord(g_side.fork, 0);
    cudaStreamWaitEvent(g_side.s, g_side.fork, 0);

    // side stream: CSR chain
    prep_kernel   <<<(n + 255) / 256, 256, 0, g_side.s>>>(n);
    deg_kernel    <<<(E + 255) / 256, 256, 0, g_side.s>>>(dst, E);
    scan1_kernel  <<<nScanBlocks, SCAN_B, 0, g_side.s>>>(n);
    scan2_kernel  <<<1, 512, 0, g_side.s>>>(nScanBlocks, n, E);
    scan3_kernel  <<<nScanBlocks, SCAN_B, 0, g_side.s>>>(n);
    scatter_kernel<<<(E + 255) / 256, 256, 0, g_side.s>>>(src, dst, E);
    cudaEventRecord(g_side.join, g_side.s);

    // main stream: conversions + GEMM1
    convall_kernel<<<(n * 32 + 255) / 256, 256>>>(x, W1, W2, n);
    tgemm_kernel<<<gemmBlocks, 512, SM_TOTAL>>>(xb_ptr, w1h, w1l, tb_ptr, n, 128);

    // join: pull1 needs CSR
    cudaStreamWaitEvent(0, g_side.join, 0);

    pull_kernel<<<pullBlocks, 256>>>(b1, n);
    tgemm_kernel<<<gemmBlocks, 512, SM_TOTAL>>>(yb_ptr, w2h, w2l, tb_ptr, n, HDIM);
    pull_kernel<<<pullBlocks, 256>>>(b2, n);

    colsum_kernel<<<592, HDIM>>>(n);
    final_kernel<<<1, HDIM>>>(Wl, bl, out, 1.0f / (float)n);
}